// round 15
// baseline (speedup 1.0000x reference)
#include <cuda_runtime.h>
#include <cuda_bf16.h>
#include <cstdint>

#define DD 256
#define NLIG 2048
#define NPRO 16384
#define NB 32
#define SPLITS 8

__device__ __forceinline__ uint32_t smem_to_u32(const void* p) {
    uint32_t a;
    asm("{ .reg .u64 t; cvta.to.shared.u64 t, %1; cvt.u32.u64 %0, t; }" : "=r"(a) : "l"(p));
    return a;
}
#define MMA_BF16(c, a, b0v, b1v) \
    asm volatile("mma.sync.aligned.m16n8k16.row.col.f32.bf16.bf16.f32 " \
        "{%0,%1,%2,%3}, {%4,%5,%6,%7}, {%8,%9}, {%0,%1,%2,%3};" \
        : "+f"((c)[0]), "+f"((c)[1]), "+f"((c)[2]), "+f"((c)[3]) \
        : "r"((a)[0]), "r"((a)[1]), "r"((a)[2]), "r"((a)[3]), "r"(b0v), "r"(b1v))
#define LDSM_X4(r, addr) \
    asm volatile("ldmatrix.sync.aligned.m8n8.x4.shared.b16 {%0,%1,%2,%3}, [%4];" \
        : "=r"((r)[0]), "=r"((r)[1]), "=r"((r)[2]), "=r"((r)[3]) : "r"(addr))
#define LDSM_X4T(r, addr) \
    asm volatile("ldmatrix.sync.aligned.m8n8.x4.trans.shared.b16 {%0,%1,%2,%3}, [%4];" \
        : "=r"((r)[0]), "=r"((r)[1]), "=r"((r)[2]), "=r"((r)[3]) : "r"(addr))
#define CP_ASYNC16(dst, src, n) \
    asm volatile("cp.async.cg.shared.global [%0], [%1], 16, %2;" \
        :: "r"(dst), "l"(src), "r"(n))
#define CP_COMMIT() asm volatile("cp.async.commit_group;" ::: "memory")
#define CP_WAIT0()  asm volatile("cp.async.wait_group 0;" ::: "memory")
#define CP_WAIT1()  asm volatile("cp.async.wait_group 1;" ::: "memory")

// ---------------- scratch ---------------------------------------------------
__device__ float g_tmpL[NLIG * DD];
__device__ float g_tmpP[NPRO * DD];
__device__ float g_ctxLp[SPLITS * NLIG * DD];
__device__ float g_denLp[SPLITS * NLIG];
__device__ int g_ls[NB], g_lc[NB], g_ps[NB], g_pc[NB];

__device__ __nv_bfloat16 g_ligH[NLIG * DD], g_ligL[NLIG * DD];
__device__ __nv_bfloat16 g_proH[NPRO * DD], g_proL[NPRO * DD];
__device__ __nv_bfloat16 g_QH [NLIG * DD], g_QL [NLIG * DD];
__device__ __nv_bfloat16 g_K2H[NLIG * DD], g_K2L[NLIG * DD];
__device__ __nv_bfloat16 g_V2H[NLIG * DD], g_V2L[NLIG * DD];
__device__ __nv_bfloat16 g_KH [NPRO * DD], g_KL [NPRO * DD];
__device__ __nv_bfloat16 g_VH [NPRO * DD], g_VL [NPRO * DD];
__device__ __nv_bfloat16 g_Q2H[NPRO * DD], g_Q2L[NPRO * DD];
__device__ __nv_bfloat16 g_cLH[NLIG * DD], g_cLL[NLIG * DD];
__device__ __nv_bfloat16 g_cPH[NPRO * DD], g_cPL[NPRO * DD];
__device__ __nv_bfloat16 g_WH [8 * DD * DD], g_WL[8 * DD * DD];

__device__ __forceinline__ void split2(float a, float b, uint32_t& hi, uint32_t& lo)
{
    __nv_bfloat16 ha = __float2bfloat16(a), hb = __float2bfloat16(b);
    __nv_bfloat162 hp = __halves2bfloat162(ha, hb);
    hi = *reinterpret_cast<uint32_t*>(&hp);
    float la = a - __bfloat162float(ha);
    float lb = b - __bfloat162float(hb);
    __nv_bfloat162 lp = __floats2bfloat162_rn(la, lb);
    lo = *reinterpret_cast<uint32_t*>(&lp);
}

struct ConvOps {
    const float* src[10];
    __nv_bfloat16 *h[10], *l[10];
    int n4[10];
};

__global__ __launch_bounds__(256) void convert_kernel(ConvOps C)
{
    const int op = blockIdx.y;
    const float* __restrict__ s = C.src[op];
    __nv_bfloat16* __restrict__ h = C.h[op];
    __nv_bfloat16* __restrict__ l = C.l[op];
    const int n4 = C.n4[op];
    for (int i = blockIdx.x * 256 + threadIdx.x; i < n4; i += gridDim.x * 256) {
        float4 f = *(const float4*)(s + i * 4);
        uint32_t h0, l0, h1, l1;
        split2(f.x, f.y, h0, l0);
        split2(f.z, f.w, h1, l1);
        *(uint2*)(h + i * 4) = make_uint2(h0, h1);
        *(uint2*)(l + i * 4) = make_uint2(l0, l1);
    }
}

__global__ void ranges_kernel(const int* __restrict__ lb, const int* __restrict__ pb)
{
    int t = threadIdx.x;
    if (t < NB) {
        int b = t, lo = 0, hi = NLIG;
        while (lo < hi) { int m = (lo + hi) >> 1; if (lb[m] < b) lo = m + 1; else hi = m; }
        int s = lo; hi = NLIG;
        while (lo < hi) { int m = (lo + hi) >> 1; if (lb[m] <= b) lo = m + 1; else hi = m; }
        g_ls[b] = s; g_lc[b] = lo - s;
    } else if (t < 2 * NB) {
        int b = t - NB, lo = 0, hi = NPRO;
        while (lo < hi) { int m = (lo + hi) >> 1; if (pb[m] < b) lo = m + 1; else hi = m; }
        int s = lo; hi = NPRO;
        while (lo < hi) { int m = (lo + hi) >> 1; if (pb[m] <= b) lo = m + 1; else hi = m; }
        g_ps[b] = s; g_pc[b] = lo - s;
    }
}

// ============ split-bf16 mma.sync GEMM, 2-stage cp.async pipeline ===========
struct MmaOps {
    const __nv_bfloat16 *Xh[6], *Xl[6], *Wh[6], *Wl[6];
    float* Y[6];
    __nv_bfloat16 *Yh[6], *Yl[6];
    float scale[6];
    int lig_ops;
};

#define GEMM_SMEM 131072

__global__ __launch_bounds__(256) void gemm_mma(MmaOps P)
{
    extern __shared__ char smc[];
    const uint32_t sb = smem_to_u32(smc);

    const int bx = blockIdx.x;
    const int ligregion = P.lig_ops * 16;
    int op, mt;
    if (bx < ligregion) { op = bx >> 4; mt = bx & 15; }
    else { int r = bx - ligregion; op = P.lig_ops + (r >> 7); mt = r & 127; }
    const __nv_bfloat16* __restrict__ Xh = P.Xh[op];
    const __nv_bfloat16* __restrict__ Xl = P.Xl[op];
    const __nv_bfloat16* __restrict__ Wh = P.Wh[op];
    const __nv_bfloat16* __restrict__ Wl = P.Wl[op];
    const int m0 = mt * 128;
    const int n0 = blockIdx.y * 128;

    const int tid = threadIdx.x, lane = tid & 31, wid = tid >> 5;
    const int warpM = wid & 3, warpN = wid >> 2;
    const int sub = lane >> 3, r8 = lane & 7;

    auto issue = [&](int kc, int s) {
        uint32_t st = sb + s * 65536;
#pragma unroll
        for (int it = 0; it < 4; ++it) {
            int idx = tid + it * 256;
            int r = idx >> 3, c8 = idx & 7;
            int byte = (r * 128 + c8 * 16) ^ ((r & 7) << 4);
            size_t goff = (size_t)(m0 + r) * DD + kc * 64 + c8 * 8;
            size_t woff = (size_t)(n0 + r) * DD + kc * 64 + c8 * 8;
            CP_ASYNC16(st + byte,         (const void*)(Xh + goff), 16);
            CP_ASYNC16(st + 16384 + byte, (const void*)(Xl + goff), 16);
            CP_ASYNC16(st + 32768 + byte, (const void*)(Wh + woff), 16);
            CP_ASYNC16(st + 49152 + byte, (const void*)(Wl + woff), 16);
        }
        CP_COMMIT();
    };

    float acc[2][8][4];
#pragma unroll
    for (int i = 0; i < 2; ++i)
#pragma unroll
        for (int j = 0; j < 8; ++j)
#pragma unroll
            for (int k = 0; k < 4; ++k) acc[i][j][k] = 0.f;

    issue(0, 0);
    for (int kc = 0; kc < 4; ++kc) {
        if (kc < 3) issue(kc + 1, (kc + 1) & 1);
        if (kc < 3) { CP_WAIT1(); } else { CP_WAIT0(); }
        __syncthreads();
        const uint32_t st = sb + (kc & 1) * 65536;
#pragma unroll
        for (int k16 = 0; k16 < 4; ++k16) {
            uint32_t a_hi[2][4], a_lo[2][4];
#pragma unroll
            for (int mt2 = 0; mt2 < 2; ++mt2) {
                int row = warpM * 32 + mt2 * 16 + (sub & 1) * 8 + r8;
                int k8  = k16 * 2 + (sub >> 1);
                uint32_t ad = st + ((row * 128 + k8 * 16) ^ ((row & 7) << 4));
                LDSM_X4(a_hi[mt2], ad);
                LDSM_X4(a_lo[mt2], ad + 16384);
            }
#pragma unroll
            for (int np = 0; np < 4; ++np) {
                int nrow = warpN * 64 + np * 16 + (sub >> 1) * 8 + r8;
                int k8   = k16 * 2 + (sub & 1);
                uint32_t bd = st + 32768 + ((nrow * 128 + k8 * 16) ^ ((nrow & 7) << 4));
                uint32_t b_hi[4], b_lo[4];
                LDSM_X4(b_hi, bd);
                LDSM_X4(b_lo, bd + 16384);
#pragma unroll
                for (int mt2 = 0; mt2 < 2; ++mt2) {
                    MMA_BF16(acc[mt2][np * 2],     a_hi[mt2], b_hi[0], b_hi[1]);
                    MMA_BF16(acc[mt2][np * 2 + 1], a_hi[mt2], b_hi[2], b_hi[3]);
                    MMA_BF16(acc[mt2][np * 2],     a_hi[mt2], b_lo[0], b_lo[1]);
                    MMA_BF16(acc[mt2][np * 2 + 1], a_hi[mt2], b_lo[2], b_lo[3]);
                    MMA_BF16(acc[mt2][np * 2],     a_lo[mt2], b_hi[0], b_hi[1]);
                    MMA_BF16(acc[mt2][np * 2 + 1], a_lo[mt2], b_hi[2], b_hi[3]);
                }
            }
        }
        __syncthreads();
    }

    const int t4 = lane >> 2, q = lane & 3;
    __nv_bfloat16* Yh = P.Yh[op];
    if (Yh) {
        __nv_bfloat16* Yl = P.Yl[op];
        const float scl = P.scale[op];
#pragma unroll
        for (int mt2 = 0; mt2 < 2; ++mt2) {
#pragma unroll
            for (int nt = 0; nt < 8; ++nt) {
                int row = m0 + warpM * 32 + mt2 * 16 + t4;
                int col = n0 + warpN * 64 + nt * 8 + q * 2;
                uint32_t h0, l0, h1, l1;
                split2(acc[mt2][nt][0] * scl, acc[mt2][nt][1] * scl, h0, l0);
                split2(acc[mt2][nt][2] * scl, acc[mt2][nt][3] * scl, h1, l1);
                *(uint32_t*)(Yh + (size_t)row * DD + col) = h0;
                *(uint32_t*)(Yl + (size_t)row * DD + col) = l0;
                *(uint32_t*)(Yh + (size_t)(row + 8) * DD + col) = h1;
                *(uint32_t*)(Yl + (size_t)(row + 8) * DD + col) = l1;
            }
        }
    } else {
        float* __restrict__ Y = P.Y[op];
#pragma unroll
        for (int mt2 = 0; mt2 < 2; ++mt2) {
#pragma unroll
            for (int nt = 0; nt < 8; ++nt) {
                float* yr = Y + (size_t)(m0 + warpM * 32 + mt2 * 16 + t4) * DD
                              + n0 + warpN * 64 + nt * 8 + q * 2;
                *(float2*)yr            = make_float2(acc[mt2][nt][0], acc[mt2][nt][1]);
                *(float2*)(yr + 8 * DD) = make_float2(acc[mt2][nt][2], acc[mt2][nt][3]);
            }
        }
    }
}

// == full-MMA flash attention: 64 queries/CTA, 512 thr, 32-key 2-stage pipe ==
// 16 warps = 4(m) x 4(n); warp S tile 16x8 keys, warp O tile 16x64.

struct AttnSide {
    const __nv_bfloat16 *Qh, *Ql, *Kh, *Kl, *Vh, *Vl;
    const float *qpos, *kpos;
    const int *qbatch, *kbatch, *kstart, *kcount;
    float *ctxp, *den;
    __nv_bfloat16 *ctxH, *ctxL;
    int nblk, nsplit, prows;
};

#define SQH 0
#define SQL 32768
#define SKV0 65536
// per stage (65536): KH +0, KL +16384, VH +32768, VL +49152
#define SPH 196608
#define SPL 204800
#define SDEN 212992
#define SQP 214016
#define SKP0 215040
#define SQB 216064
#define SKB0 216320
#define ATTN_SMEM 216576

#define SWZ(g, r) ((((g) & 24) | (((g) ^ (r)) & 7)) << 4)

__global__ __launch_bounds__(512) void attn_mma(AttnSide A0, AttnSide A1)
{
    extern __shared__ char smx[];
    const uint32_t sb = smem_to_u32(smx);
    float* den4 = (float*)(smx + SDEN);   // [4][64]
    float* qpS  = (float*)(smx + SQP);
    int*   qbS  = (int*)(smx + SQB);

    const bool first = (blockIdx.x < (unsigned)A0.nblk);
    AttnSide S = first ? A0 : A1;
    const int blk  = first ? blockIdx.x : blockIdx.x - A0.nblk;
    const int sp   = (S.nsplit > 1) ? blk % S.nsplit : 0;
    const int qblk = (S.nsplit > 1) ? blk / S.nsplit : blk;
    const int tid = threadIdx.x, lane = tid & 31, wid = tid >> 5;
    const int wm = wid & 3, wn = wid >> 2;
    const int sub = lane >> 3, r8 = lane & 7;
    const int t4 = lane >> 2, qq = lane & 3;
    const int q0 = qblk * 64;

    // stage Q (both planes, swizzled, cp.async) + qb/qp; zero den partials
#pragma unroll
    for (int it = 0; it < 8; ++it) {
        int idx = tid + it * 512;
        int pl = idx >> 11, r = (idx >> 5) & 63, g = idx & 31;
        uint32_t dst = sb + (pl ? SQL : SQH) + r * 512 + SWZ(g, r);
        const void* src = (pl ? S.Ql : S.Qh) + (size_t)(q0 + r) * DD + g * 8;
        CP_ASYNC16(dst, src, 16);
    }
    CP_COMMIT();
    if (tid < 256) den4[tid] = 0.f;
    if (tid < 64) {
        int r = q0 + tid;
        qbS[tid] = S.qbatch[r];
        qpS[tid * 4 + 0] = S.qpos[r * 3 + 0];
        qpS[tid * 4 + 1] = S.qpos[r * 3 + 1];
        qpS[tid * 4 + 2] = S.qpos[r * 3 + 2];
        qpS[tid * 4 + 3] = 0.f;
    }
    CP_WAIT0();
    __syncthreads();

    const int js = S.kstart[qbS[0]];
    const int bL = qbS[63];
    const int je = S.kstart[bL] + S.kcount[bL];
    const int nch = (je - js + 31) >> 5;
    const int cA = (S.nsplit > 1) ? (sp * nch) / S.nsplit : 0;
    const int cB = (S.nsplit > 1) ? ((sp + 1) * nch) / S.nsplit : nch;

    auto issue_kv = [&](int c, int s) {
        const int j0 = js + c * 32;
        uint32_t st = sb + SKV0 + s * 65536;
#pragma unroll
        for (int it = 0; it < 8; ++it) {
            int idx = tid + it * 512;
            int sel = idx >> 10, r = (idx >> 5) & 31, g = idx & 31;
            int gj = j0 + r;
            const __nv_bfloat16* bp = (sel == 0) ? S.Kh : (sel == 1) ? S.Kl
                                      : (sel == 2) ? S.Vh : S.Vl;
            uint32_t dst = st + sel * 16384 + r * 512 + SWZ(g, r);
            const void* src = bp + (size_t)gj * DD + g * 8;
            CP_ASYNC16(dst, src, (gj < je) ? 16 : 0);
        }
        if (tid < 32) {
            int gj = j0 + tid;
            int* kb = (int*)(smx + SKB0 + s * 128);
            float* kp = (float*)(smx + SKP0 + s * 512);
            if (gj < je) {
                kb[tid] = S.kbatch[gj];
                kp[tid * 4 + 0] = S.kpos[gj * 3 + 0];
                kp[tid * 4 + 1] = S.kpos[gj * 3 + 1];
                kp[tid * 4 + 2] = S.kpos[gj * 3 + 2];
            } else {
                kb[tid] = -1;
                kp[tid * 4 + 0] = 0.f; kp[tid * 4 + 1] = 0.f; kp[tid * 4 + 2] = 0.f;
            }
        }
        CP_COMMIT();
    };

    const int er0 = wm * 16 + t4, er1 = er0 + 8;
    const int arow = wm * 16 + (sub & 1) * 8 + r8;
    const float qx0 = qpS[er0 * 4], qy0 = qpS[er0 * 4 + 1], qz0 = qpS[er0 * 4 + 2];
    const float qx1 = qpS[er1 * 4], qy1 = qpS[er1 * 4 + 1], qz1 = qpS[er1 * 4 + 2];
    const int qb0 = qbS[er0], qb1 = qbS[er1];

    float cO[8][4];
#pragma unroll
    for (int i = 0; i < 8; ++i)
#pragma unroll
        for (int j = 0; j < 4; ++j) cO[i][j] = 0.f;

    if (cA < cB) issue_kv(cA, 0);
    for (int c = cA; c < cB; ++c) {
        const int s = (c - cA) & 1;
        if (c + 1 < cB) issue_kv(c + 1, s ^ 1);
        if (c + 1 < cB) { CP_WAIT1(); } else { CP_WAIT0(); }
        __syncthreads();
        const uint32_t SK = sb + SKV0 + s * 65536;
        const int* kbS = (const int*)(smx + SKB0 + s * 128);
        const float* kpS = (const float*)(smx + SKP0 + s * 512);

        // ---- S = Q @ K^T : warp tile 16x8 over k=256 ----
        float cS[4] = {0.f, 0.f, 0.f, 0.f};
        const int bRow = wn * 8 + (lane & 7);
#pragma unroll
        for (int ks2 = 0; ks2 < 8; ++ks2) {
            uint32_t aH0[4], aL0[4], aH1[4], aL1[4], bh[4], bl[4];
            int ag0 = ks2 * 4 + (sub >> 1);
            uint32_t ao0 = sb + SQH + arow * 512 + SWZ(ag0, arow);
            LDSM_X4(aH0, ao0);
            LDSM_X4(aL0, ao0 + 32768);
            int ag1 = ks2 * 4 + 2 + (sub >> 1);
            uint32_t ao1 = sb + SQH + arow * 512 + SWZ(ag1, arow);
            LDSM_X4(aH1, ao1);
            LDSM_X4(aL1, ao1 + 32768);
            int bg = ks2 * 4 + (lane >> 3);
            uint32_t bo = SK + bRow * 512 + SWZ(bg, bRow);
            LDSM_X4(bh, bo);
            LDSM_X4(bl, bo + 16384);
            MMA_BF16(cS, aH0, bh[0], bh[1]);
            MMA_BF16(cS, aH0, bl[0], bl[1]);
            MMA_BF16(cS, aL0, bh[0], bh[1]);
            MMA_BF16(cS, aH1, bh[2], bh[3]);
            MMA_BF16(cS, aH1, bl[2], bl[3]);
            MMA_BF16(cS, aL1, bh[2], bh[3]);
        }

        // ---- softmax weights, write P hi/lo, accumulate denominators ----
        {
            int kc = wn * 8 + qq * 2;
            float p[4];
#pragma unroll
            for (int e = 0; e < 4; ++e) {
                int cc = kc + (e & 1);
                float qx = (e < 2) ? qx0 : qx1, qy = (e < 2) ? qy0 : qy1;
                float qz = (e < 2) ? qz0 : qz1;
                int qbv = (e < 2) ? qb0 : qb1;
                float dx = qx - kpS[cc * 4], dy = qy - kpS[cc * 4 + 1];
                float dz = qz - kpS[cc * 4 + 2];
                float d2 = fmaxf(fmaf(dx, dx, fmaf(dy, dy, dz * dz)), 1e-12f);
                p[e] = (qbv == kbS[cc])
                       ? __expf(cS[e] + __expf(-0.1f * sqrtf(d2))) : 0.f;
            }
            float rs0 = p[0] + p[1], rs1 = p[2] + p[3];
            uint32_t h0, l0, h1, l1;
            split2(p[0], p[1], h0, l0);
            split2(p[2], p[3], h1, l1);
            int o0 = er0 * 128 + (((wn ^ (er0 & 7)) & 7) << 4) + qq * 4;
            int o1 = er1 * 128 + (((wn ^ (er1 & 7)) & 7) << 4) + qq * 4;
            *(uint32_t*)(smx + SPH + o0) = h0; *(uint32_t*)(smx + SPL + o0) = l0;
            *(uint32_t*)(smx + SPH + o1) = h1; *(uint32_t*)(smx + SPL + o1) = l1;
            rs0 += __shfl_xor_sync(0xffffffffu, rs0, 1);
            rs0 += __shfl_xor_sync(0xffffffffu, rs0, 2);
            rs1 += __shfl_xor_sync(0xffffffffu, rs1, 1);
            rs1 += __shfl_xor_sync(0xffffffffu, rs1, 2);
            if (qq == 0) { den4[wn * 64 + er0] += rs0; den4[wn * 64 + er1] += rs1; }
        }
        __syncthreads();

        // ---- O += P @ V : warp tile 16x64 over k=32 keys ----
#pragma unroll
        for (int ks = 0; ks < 2; ++ks) {
            uint32_t ph[4], pl[4];
            int pg = ks * 2 + (sub >> 1);
            uint32_t po = sb + SPH + arow * 128 + (((pg ^ (arow & 7)) & 7) << 4);
            LDSM_X4(ph, po);
            LDSM_X4(pl, po + 8192);
            int key = ks * 16 + (sub & 1) * 8 + r8;
#pragma unroll
            for (int nt2 = 0; nt2 < 4; ++nt2) {
                int ng = wn * 8 + nt2 * 2 + (sub >> 1);
                uint32_t vo = SK + 32768 + key * 512 + SWZ(ng, key);
                uint32_t vh[4], vl[4];
                LDSM_X4T(vh, vo);
                LDSM_X4T(vl, vo + 16384);
                MMA_BF16(cO[nt2 * 2],     ph, vh[0], vh[1]);
                MMA_BF16(cO[nt2 * 2 + 1], ph, vh[2], vh[3]);
                MMA_BF16(cO[nt2 * 2],     ph, vl[0], vl[1]);
                MMA_BF16(cO[nt2 * 2 + 1], ph, vl[2], vl[3]);
                MMA_BF16(cO[nt2 * 2],     pl, vh[0], vh[1]);
                MMA_BF16(cO[nt2 * 2 + 1], pl, vh[2], vh[3]);
            }
        }
        __syncthreads();
    }

    float d0 = den4[er0] + den4[64 + er0] + den4[128 + er0] + den4[192 + er0];
    float d1 = den4[er1] + den4[64 + er1] + den4[128 + er1] + den4[192 + er1];
    if (S.nsplit == 1) {
        float i0 = 1.0f / d0, i1 = 1.0f / d1;
#pragma unroll
        for (int nt = 0; nt < 8; ++nt) {
            int col = wn * 64 + nt * 8 + qq * 2;
            uint32_t h0, l0, h1, l1;
            split2(cO[nt][0] * i0, cO[nt][1] * i0, h0, l0);
            split2(cO[nt][2] * i1, cO[nt][3] * i1, h1, l1);
            *(uint32_t*)(S.ctxH + (size_t)(q0 + er0) * DD + col) = h0;
            *(uint32_t*)(S.ctxL + (size_t)(q0 + er0) * DD + col) = l0;
            *(uint32_t*)(S.ctxH + (size_t)(q0 + er1) * DD + col) = h1;
            *(uint32_t*)(S.ctxL + (size_t)(q0 + er1) * DD + col) = l1;
        }
    } else {
        size_t base = (size_t)sp * S.prows;
#pragma unroll
        for (int nt = 0; nt < 8; ++nt) {
            int col = wn * 64 + nt * 8 + qq * 2;
            *(float2*)(S.ctxp + (base + q0 + er0) * DD + col) =
                make_float2(cO[nt][0], cO[nt][1]);
            *(float2*)(S.ctxp + (base + q0 + er1) * DD + col) =
                make_float2(cO[nt][2], cO[nt][3]);
        }
        if (tid < 64)
            S.den[base + q0 + tid] =
                den4[tid] + den4[64 + tid] + den4[128 + tid] + den4[192 + tid];
    }
}

// ---------------- merge lig split-K partials -> bf16 hi/lo -------------------
__global__ __launch_bounds__(128) void norm_kernel(
    const float* __restrict__ part, const float* __restrict__ den,
    __nv_bfloat16* __restrict__ ctxH, __nv_bfloat16* __restrict__ ctxL)
{
    const int row = blockIdx.x * 4 + (threadIdx.x >> 5);
    const int lane = threadIdx.x & 31;
    float d = 0.f;
#pragma unroll
    for (int s = 0; s < SPLITS; ++s) d += den[s * NLIG + row];
    const float inv = 1.0f / d;
#pragma unroll
    for (int h = 0; h < 2; ++h) {
        int c = lane * 4 + h * 128;
        float4 a = make_float4(0.f, 0.f, 0.f, 0.f);
#pragma unroll
        for (int s = 0; s < SPLITS; ++s) {
            float4 v = *(const float4*)(part + ((size_t)s * NLIG + row) * DD + c);
            a.x += v.x; a.y += v.y; a.z += v.z; a.w += v.w;
        }
        uint32_t h0, l0, h1, l1;
        split2(a.x * inv, a.y * inv, h0, l0);
        split2(a.z * inv, a.w * inv, h1, l1);
        *(uint2*)(ctxH + (size_t)row * DD + c) = make_uint2(h0, h1);
        *(uint2*)(ctxL + (size_t)row * DD + c) = make_uint2(l0, l1);
    }
}

// ---------------- residual + bias + layernorm -------------------------------
__global__ __launch_bounds__(128) void ln2_kernel(
    const float* __restrict__ lig, const float* __restrict__ pro,
    const float* __restrict__ tL, const float* __restrict__ tP,
    const float* __restrict__ boutL, const float* __restrict__ boutP,
    const float* __restrict__ gL, const float* __restrict__ bL,
    const float* __restrict__ gP, const float* __restrict__ bP,
    float* __restrict__ out)
{
    const int row = blockIdx.x * 4 + (threadIdx.x >> 5);
    const int lane = threadIdx.x & 31;
    const float *x, *y, *bias, *g, *bb;
    if (row < NLIG) {
        x = lig + (size_t)row * DD; y = tL + (size_t)row * DD;
        bias = boutL; g = gL; bb = bL;
    } else {
        int r = row - NLIG;
        x = pro + (size_t)r * DD; y = tP + (size_t)r * DD;
        bias = boutP; g = gP; bb = bP;
    }
    float t[8];
#pragma unroll
    for (int i = 0; i < 8; ++i) {
        int c = lane * 8 + i;
        t[i] = x[c] + y[c] + bias[c];
    }
    float s = 0.f;
#pragma unroll
    for (int i = 0; i < 8; ++i) s += t[i];
#pragma unroll
    for (int off = 16; off; off >>= 1) s += __shfl_xor_sync(0xffffffffu, s, off);
    float mu = s * (1.0f / DD);
    float v = 0.f;
#pragma unroll
    for (int i = 0; i < 8; ++i) { float d = t[i] - mu; v += d * d; }
#pragma unroll
    for (int off = 16; off; off >>= 1) v += __shfl_xor_sync(0xffffffffu, v, off);
    float r = rsqrtf(v * (1.0f / DD) + 1e-5f);
#pragma unroll
    for (int i = 0; i < 8; ++i) {
        int c = lane * 8 + i;
        out[(size_t)row * DD + c] = (t[i] - mu) * r * g[c] + bb[c];
    }
}

// ---------------- launch ----------------------------------------------------
extern "C" void kernel_launch(void* const* d_in, const int* in_sizes, int n_in,
                              void* d_out, int out_size)
{
    const float* lig      = (const float*)d_in[0];
    const float* pro      = (const float*)d_in[1];
    const float* lig_pos  = (const float*)d_in[2];
    const float* pro_pos  = (const float*)d_in[3];
    const int*   lig_batch= (const int*)  d_in[4];
    const int*   pro_batch= (const int*)  d_in[5];
    const float* Wq_lig   = (const float*)d_in[6];
    const float* Wk_pro   = (const float*)d_in[7];
    const float* Wv_pro   = (const float*)d_in[8];
    const float* Wq_pro   = (const float*)d_in[9];
    const float* Wk_lig   = (const float*)d_in[10];
    const float* Wv_lig   = (const float*)d_in[11];
    const float* Wout_lig = (const float*)d_in[12];
    const float* bout_lig = (const float*)d_in[13];
    const float* Wout_pro = (const float*)d_in[14];
    const float* bout_pro = (const float*)d_in[15];
    const float* gl       = (const float*)d_in[16];
    const float* bl       = (const float*)d_in[17];
    const float* gp       = (const float*)d_in[18];
    const float* bp       = (const float*)d_in[19];
    float* out = (float*)d_out;

    float *tmpL, *tmpP, *ctxLp, *denLp;
    int *ls, *lc, *ps, *pc;
    __nv_bfloat16 *ligH, *ligL, *proH, *proL, *WH, *WL;
    __nv_bfloat16 *QH, *QL, *K2H, *K2L, *V2H, *V2L, *KH, *KL, *VH, *VL, *Q2H, *Q2L;
    __nv_bfloat16 *cLH, *cLL, *cPH, *cPL;
    cudaGetSymbolAddress((void**)&tmpL, g_tmpL);
    cudaGetSymbolAddress((void**)&tmpP, g_tmpP);
    cudaGetSymbolAddress((void**)&ctxLp, g_ctxLp);
    cudaGetSymbolAddress((void**)&denLp, g_denLp);
    cudaGetSymbolAddress((void**)&ls, g_ls);
    cudaGetSymbolAddress((void**)&lc, g_lc);
    cudaGetSymbolAddress((void**)&ps, g_ps);
    cudaGetSymbolAddress((void**)&pc, g_pc);
    cudaGetSymbolAddress((void**)&ligH, g_ligH);
    cudaGetSymbolAddress((void**)&ligL, g_ligL);
    cudaGetSymbolAddress((void**)&proH, g_proH);
    cudaGetSymbolAddress((void**)&proL, g_proL);
    cudaGetSymbolAddress((void**)&WH, g_WH);
    cudaGetSymbolAddress((void**)&WL, g_WL);
    cudaGetSymbolAddress((void**)&QH, g_QH);   cudaGetSymbolAddress((void**)&QL, g_QL);
    cudaGetSymbolAddress((void**)&K2H, g_K2H); cudaGetSymbolAddress((void**)&K2L, g_K2L);
    cudaGetSymbolAddress((void**)&V2H, g_V2H); cudaGetSymbolAddress((void**)&V2L, g_V2L);
    cudaGetSymbolAddress((void**)&KH, g_KH);   cudaGetSymbolAddress((void**)&KL, g_KL);
    cudaGetSymbolAddress((void**)&VH, g_VH);   cudaGetSymbolAddress((void**)&VL, g_VL);
    cudaGetSymbolAddress((void**)&Q2H, g_Q2H); cudaGetSymbolAddress((void**)&Q2L, g_Q2L);
    cudaGetSymbolAddress((void**)&cLH, g_cLH); cudaGetSymbolAddress((void**)&cLL, g_cLL);
    cudaGetSymbolAddress((void**)&cPH, g_cPH); cudaGetSymbolAddress((void**)&cPL, g_cPL);

    cudaFuncSetAttribute(gemm_mma, cudaFuncAttributeMaxDynamicSharedMemorySize, GEMM_SMEM);
    cudaFuncSetAttribute(attn_mma, cudaFuncAttributeMaxDynamicSharedMemorySize, ATTN_SMEM);

    ranges_kernel<<<1, 64>>>(lig_batch, pro_batch);

    const float* Wsrc[8] = {Wq_lig, Wk_lig, Wv_lig, Wk_pro, Wv_pro, Wq_pro, Wout_lig, Wout_pro};
    ConvOps c1;
    c1.src[0] = lig; c1.h[0] = ligH; c1.l[0] = ligL; c1.n4[0] = NLIG * DD / 4;
    c1.src[1] = pro; c1.h[1] = proH; c1.l[1] = proL; c1.n4[1] = NPRO * DD / 4;
    for (int i = 0; i < 8; ++i) {
        c1.src[2 + i] = Wsrc[i];
        c1.h[2 + i] = WH + i * DD * DD;
        c1.l[2 + i] = WL + i * DD * DD;
        c1.n4[2 + i] = DD * DD / 4;
    }
    convert_kernel<<<dim3(128, 10), 256>>>(c1);

    // QKV projections -> bf16 hi/lo planes (Q sides pre-scaled by 1/16)
    MmaOps gq;
    for (int i = 0; i < 3; ++i) { gq.Xh[i] = ligH; gq.Xl[i] = ligL; }
    for (int i = 3; i < 6; ++i) { gq.Xh[i] = proH; gq.Xl[i] = proL; }
    for (int i = 0; i < 6; ++i) {
        gq.Wh[i] = WH + i * DD * DD;
        gq.Wl[i] = WL + i * DD * DD;
        gq.Y[i] = nullptr;
        gq.scale[i] = 1.0f;
    }
    gq.Yh[0] = QH;  gq.Yl[0] = QL;  gq.scale[0] = 0.0625f;
    gq.Yh[1] = K2H; gq.Yl[1] = K2L;
    gq.Yh[2] = V2H; gq.Yl[2] = V2L;
    gq.Yh[3] = KH;  gq.Yl[3] = KL;
    gq.Yh[4] = VH;  gq.Yl[4] = VL;
    gq.Yh[5] = Q2H; gq.Yl[5] = Q2L; gq.scale[5] = 0.0625f;
    gq.lig_ops = 3;
    gemm_mma<<<dim3(3 * 16 + 3 * 128, 2), 256, GEMM_SMEM>>>(gq);

    // attention (lig split-K x8 first, then pro); 64 queries per block
    AttnSide aL, aP;
    aL.Qh = QH; aL.Ql = QL; aL.Kh = KH; aL.Kl = KL; aL.Vh = VH; aL.Vl = VL;
    aL.qpos = lig_pos; aL.kpos = pro_pos;
    aL.qbatch = lig_batch; aL.kbatch = pro_batch; aL.kstart = ps; aL.kcount = pc;
    aL.ctxp = ctxLp; aL.den = denLp; aL.ctxH = cLH; aL.ctxL = cLL;
    aL.nblk = (NLIG / 64) * SPLITS; aL.nsplit = SPLITS; aL.prows = NLIG;
    aP.Qh = Q2H; aP.Ql = Q2L; aP.Kh = K2H; aP.Kl = K2L; aP.Vh = V2H; aP.Vl = V2L;
    aP.qpos = pro_pos; aP.kpos = lig_pos;
    aP.qbatch = pro_batch; aP.kbatch = lig_batch; aP.kstart = ls; aP.kcount = lc;
    aP.ctxp = ctxLp; aP.den = denLp; aP.ctxH = cPH; aP.ctxL = cPL;
    aP.nblk = NPRO / 64; aP.nsplit = 1; aP.prows = NPRO;
    attn_mma<<<aL.nblk + aP.nblk, 512, ATTN_SMEM>>>(aL, aP);

    norm_kernel<<<NLIG / 4, 128>>>(ctxLp, denLp, cLH, cLL);

    // output projections (fp32 epilogue)
    MmaOps go;
    for (int i = 0; i < 6; ++i) {
        go.Xh[i] = cLH; go.Xl[i] = cLL;
        go.Wh[i] = WH + 6 * DD * DD; go.Wl[i] = WL + 6 * DD * DD;
        go.Y[i] = tmpL; go.Yh[i] = nullptr; go.Yl[i] = nullptr;
        go.scale[i] = 1.0f;
    }
    go.Xh[1] = cPH; go.Xl[1] = cPL;
    go.Wh[1] = WH + 7 * DD * DD; go.Wl[1] = WL + 7 * DD * DD;
    go.Y[1] = tmpP;
    go.lig_ops = 1;
    gemm_mma<<<dim3(16 + 128, 2), 256, GEMM_SMEM>>>(go);

    ln2_kernel<<<(NLIG + NPRO) / 4, 128>>>(lig, pro, tmpL, tmpP,
                                           bout_lig, bout_pro, gl, bl, gp, bp, out);
}

// round 16
// speedup vs baseline: 1.0602x; 1.0602x over previous
#include <cuda_runtime.h>
#include <cuda_bf16.h>
#include <cstdint>

#define DD 256
#define NLIG 2048
#define NPRO 16384
#define NB 32
#define SPLITS 4

__device__ __forceinline__ uint32_t smem_to_u32(const void* p) {
    uint32_t a;
    asm("{ .reg .u64 t; cvta.to.shared.u64 t, %1; cvt.u32.u64 %0, t; }" : "=r"(a) : "l"(p));
    return a;
}
#define MMA_BF16(c, a, b0v, b1v) \
    asm volatile("mma.sync.aligned.m16n8k16.row.col.f32.bf16.bf16.f32 " \
        "{%0,%1,%2,%3}, {%4,%5,%6,%7}, {%8,%9}, {%0,%1,%2,%3};" \
        : "+f"((c)[0]), "+f"((c)[1]), "+f"((c)[2]), "+f"((c)[3]) \
        : "r"((a)[0]), "r"((a)[1]), "r"((a)[2]), "r"((a)[3]), "r"(b0v), "r"(b1v))
#define LDSM_X4(r, addr) \
    asm volatile("ldmatrix.sync.aligned.m8n8.x4.shared.b16 {%0,%1,%2,%3}, [%4];" \
        : "=r"((r)[0]), "=r"((r)[1]), "=r"((r)[2]), "=r"((r)[3]) : "r"(addr))
#define LDSM_X4T(r, addr) \
    asm volatile("ldmatrix.sync.aligned.m8n8.x4.trans.shared.b16 {%0,%1,%2,%3}, [%4];" \
        : "=r"((r)[0]), "=r"((r)[1]), "=r"((r)[2]), "=r"((r)[3]) : "r"(addr))
#define CP_ASYNC16(dst, src, n) \
    asm volatile("cp.async.cg.shared.global [%0], [%1], 16, %2;" \
        :: "r"(dst), "l"(src), "r"(n))
#define CP_COMMIT() asm volatile("cp.async.commit_group;" ::: "memory")
#define CP_WAIT0()  asm volatile("cp.async.wait_group 0;" ::: "memory")
#define CP_WAIT1()  asm volatile("cp.async.wait_group 1;" ::: "memory")

// ---------------- scratch ---------------------------------------------------
__device__ float g_tmpL[NLIG * DD];
__device__ float g_tmpP[NPRO * DD];
__device__ float g_ctxLp[SPLITS * NLIG * DD];
__device__ float g_denLp[SPLITS * NLIG];
__device__ int g_ls[NB], g_lc[NB], g_ps[NB], g_pc[NB];

__device__ __nv_bfloat16 g_ligH[NLIG * DD], g_ligL[NLIG * DD];
__device__ __nv_bfloat16 g_proH[NPRO * DD], g_proL[NPRO * DD];
__device__ __nv_bfloat16 g_QH [NLIG * DD], g_QL [NLIG * DD];
__device__ __nv_bfloat16 g_K2H[NLIG * DD], g_K2L[NLIG * DD];
__device__ __nv_bfloat16 g_V2H[NLIG * DD], g_V2L[NLIG * DD];
__device__ __nv_bfloat16 g_KH [NPRO * DD], g_KL [NPRO * DD];
__device__ __nv_bfloat16 g_VH [NPRO * DD], g_VL [NPRO * DD];
__device__ __nv_bfloat16 g_Q2H[NPRO * DD], g_Q2L[NPRO * DD];
__device__ __nv_bfloat16 g_cLH[NLIG * DD], g_cLL[NLIG * DD];
__device__ __nv_bfloat16 g_cPH[NPRO * DD], g_cPL[NPRO * DD];
__device__ __nv_bfloat16 g_WH [8 * DD * DD], g_WL[8 * DD * DD];

__device__ __forceinline__ void split2(float a, float b, uint32_t& hi, uint32_t& lo)
{
    __nv_bfloat16 ha = __float2bfloat16(a), hb = __float2bfloat16(b);
    __nv_bfloat162 hp = __halves2bfloat162(ha, hb);
    hi = *reinterpret_cast<uint32_t*>(&hp);
    float la = a - __bfloat162float(ha);
    float lb = b - __bfloat162float(hb);
    __nv_bfloat162 lp = __floats2bfloat162_rn(la, lb);
    lo = *reinterpret_cast<uint32_t*>(&lp);
}

struct ConvOps {
    const float* src[10];
    __nv_bfloat16 *h[10], *l[10];
    int n4[10];
};

__global__ __launch_bounds__(256) void convert_kernel(ConvOps C)
{
    const int op = blockIdx.y;
    const float* __restrict__ s = C.src[op];
    __nv_bfloat16* __restrict__ h = C.h[op];
    __nv_bfloat16* __restrict__ l = C.l[op];
    const int n4 = C.n4[op];
    for (int i = blockIdx.x * 256 + threadIdx.x; i < n4; i += gridDim.x * 256) {
        float4 f = *(const float4*)(s + i * 4);
        uint32_t h0, l0, h1, l1;
        split2(f.x, f.y, h0, l0);
        split2(f.z, f.w, h1, l1);
        *(uint2*)(h + i * 4) = make_uint2(h0, h1);
        *(uint2*)(l + i * 4) = make_uint2(l0, l1);
    }
}

__global__ void ranges_kernel(const int* __restrict__ lb, const int* __restrict__ pb)
{
    int t = threadIdx.x;
    if (t < NB) {
        int b = t, lo = 0, hi = NLIG;
        while (lo < hi) { int m = (lo + hi) >> 1; if (lb[m] < b) lo = m + 1; else hi = m; }
        int s = lo; hi = NLIG;
        while (lo < hi) { int m = (lo + hi) >> 1; if (lb[m] <= b) lo = m + 1; else hi = m; }
        g_ls[b] = s; g_lc[b] = lo - s;
    } else if (t < 2 * NB) {
        int b = t - NB, lo = 0, hi = NPRO;
        while (lo < hi) { int m = (lo + hi) >> 1; if (pb[m] < b) lo = m + 1; else hi = m; }
        int s = lo; hi = NPRO;
        while (lo < hi) { int m = (lo + hi) >> 1; if (pb[m] <= b) lo = m + 1; else hi = m; }
        g_ps[b] = s; g_pc[b] = lo - s;
    }
}

// ============ split-bf16 mma.sync GEMM, 2-stage cp.async pipeline ===========
struct MmaOps {
    const __nv_bfloat16 *Xh[6], *Xl[6], *Wh[6], *Wl[6];
    float* Y[6];
    __nv_bfloat16 *Yh[6], *Yl[6];
    float scale[6];
    int lig_ops;
};

#define GEMM_SMEM 131072

__global__ __launch_bounds__(256) void gemm_mma(MmaOps P)
{
    extern __shared__ char smc[];
    const uint32_t sb = smem_to_u32(smc);

    const int bx = blockIdx.x;
    const int ligregion = P.lig_ops * 16;
    int op, mt;
    if (bx < ligregion) { op = bx >> 4; mt = bx & 15; }
    else { int r = bx - ligregion; op = P.lig_ops + (r >> 7); mt = r & 127; }
    const __nv_bfloat16* __restrict__ Xh = P.Xh[op];
    const __nv_bfloat16* __restrict__ Xl = P.Xl[op];
    const __nv_bfloat16* __restrict__ Wh = P.Wh[op];
    const __nv_bfloat16* __restrict__ Wl = P.Wl[op];
    const int m0 = mt * 128;
    const int n0 = blockIdx.y * 128;

    const int tid = threadIdx.x, lane = tid & 31, wid = tid >> 5;
    const int warpM = wid & 3, warpN = wid >> 2;
    const int sub = lane >> 3, r8 = lane & 7;

    auto issue = [&](int kc, int s) {
        uint32_t st = sb + s * 65536;
#pragma unroll
        for (int it = 0; it < 4; ++it) {
            int idx = tid + it * 256;
            int r = idx >> 3, c8 = idx & 7;
            int byte = (r * 128 + c8 * 16) ^ ((r & 7) << 4);
            size_t goff = (size_t)(m0 + r) * DD + kc * 64 + c8 * 8;
            size_t woff = (size_t)(n0 + r) * DD + kc * 64 + c8 * 8;
            CP_ASYNC16(st + byte,         (const void*)(Xh + goff), 16);
            CP_ASYNC16(st + 16384 + byte, (const void*)(Xl + goff), 16);
            CP_ASYNC16(st + 32768 + byte, (const void*)(Wh + woff), 16);
            CP_ASYNC16(st + 49152 + byte, (const void*)(Wl + woff), 16);
        }
        CP_COMMIT();
    };

    float acc[2][8][4];
#pragma unroll
    for (int i = 0; i < 2; ++i)
#pragma unroll
        for (int j = 0; j < 8; ++j)
#pragma unroll
            for (int k = 0; k < 4; ++k) acc[i][j][k] = 0.f;

    issue(0, 0);
    for (int kc = 0; kc < 4; ++kc) {
        if (kc < 3) issue(kc + 1, (kc + 1) & 1);
        if (kc < 3) { CP_WAIT1(); } else { CP_WAIT0(); }
        __syncthreads();
        const uint32_t st = sb + (kc & 1) * 65536;
#pragma unroll
        for (int k16 = 0; k16 < 4; ++k16) {
            uint32_t a_hi[2][4], a_lo[2][4];
#pragma unroll
            for (int mt2 = 0; mt2 < 2; ++mt2) {
                int row = warpM * 32 + mt2 * 16 + (sub & 1) * 8 + r8;
                int k8  = k16 * 2 + (sub >> 1);
                uint32_t ad = st + ((row * 128 + k8 * 16) ^ ((row & 7) << 4));
                LDSM_X4(a_hi[mt2], ad);
                LDSM_X4(a_lo[mt2], ad + 16384);
            }
#pragma unroll
            for (int np = 0; np < 4; ++np) {
                int nrow = warpN * 64 + np * 16 + (sub >> 1) * 8 + r8;
                int k8   = k16 * 2 + (sub & 1);
                uint32_t bd = st + 32768 + ((nrow * 128 + k8 * 16) ^ ((nrow & 7) << 4));
                uint32_t b_hi[4], b_lo[4];
                LDSM_X4(b_hi, bd);
                LDSM_X4(b_lo, bd + 16384);
#pragma unroll
                for (int mt2 = 0; mt2 < 2; ++mt2) {
                    MMA_BF16(acc[mt2][np * 2],     a_hi[mt2], b_hi[0], b_hi[1]);
                    MMA_BF16(acc[mt2][np * 2 + 1], a_hi[mt2], b_hi[2], b_hi[3]);
                    MMA_BF16(acc[mt2][np * 2],     a_hi[mt2], b_lo[0], b_lo[1]);
                    MMA_BF16(acc[mt2][np * 2 + 1], a_hi[mt2], b_lo[2], b_lo[3]);
                    MMA_BF16(acc[mt2][np * 2],     a_lo[mt2], b_hi[0], b_hi[1]);
                    MMA_BF16(acc[mt2][np * 2 + 1], a_lo[mt2], b_hi[2], b_hi[3]);
                }
            }
        }
        __syncthreads();
    }

    const int t4 = lane >> 2, q = lane & 3;
    __nv_bfloat16* Yh = P.Yh[op];
    if (Yh) {
        __nv_bfloat16* Yl = P.Yl[op];
        const float scl = P.scale[op];
#pragma unroll
        for (int mt2 = 0; mt2 < 2; ++mt2) {
#pragma unroll
            for (int nt = 0; nt < 8; ++nt) {
                int row = m0 + warpM * 32 + mt2 * 16 + t4;
                int col = n0 + warpN * 64 + nt * 8 + q * 2;
                uint32_t h0, l0, h1, l1;
                split2(acc[mt2][nt][0] * scl, acc[mt2][nt][1] * scl, h0, l0);
                split2(acc[mt2][nt][2] * scl, acc[mt2][nt][3] * scl, h1, l1);
                *(uint32_t*)(Yh + (size_t)row * DD + col) = h0;
                *(uint32_t*)(Yl + (size_t)row * DD + col) = l0;
                *(uint32_t*)(Yh + (size_t)(row + 8) * DD + col) = h1;
                *(uint32_t*)(Yl + (size_t)(row + 8) * DD + col) = l1;
            }
        }
    } else {
        float* __restrict__ Y = P.Y[op];
#pragma unroll
        for (int mt2 = 0; mt2 < 2; ++mt2) {
#pragma unroll
            for (int nt = 0; nt < 8; ++nt) {
                float* yr = Y + (size_t)(m0 + warpM * 32 + mt2 * 16 + t4) * DD
                              + n0 + warpN * 64 + nt * 8 + q * 2;
                *(float2*)yr            = make_float2(acc[mt2][nt][0], acc[mt2][nt][1]);
                *(float2*)(yr + 8 * DD) = make_float2(acc[mt2][nt][2], acc[mt2][nt][3]);
            }
        }
    }
}

// == full-MMA flash attention: 32q/CTA, 64-key chunks, phase-ordered prefetch ==
// 8 warps = 2(m) x 4(n). K(c+1) issued after S(c) (lands during PV);
// V(c+1) issued after PV(c) (lands during S(c+1)). In-place, no extra smem.

struct AttnSide {
    const __nv_bfloat16 *Qh, *Ql, *Kh, *Kl, *Vh, *Vl;
    const float *qpos, *kpos;
    const int *qbatch, *kbatch, *kstart, *kcount;
    float *ctxp, *den;
    __nv_bfloat16 *ctxH, *ctxL;
    int nblk, nsplit, prows;
};

#define SQH 0
#define SQL 16384
#define SKH 32768
#define SKL 65536
#define SVH 98304
#define SVL 131072
#define SPH 163840
#define SPL 167936
#define SDEN 172032
#define SQP 172544
#define SKP 173056
#define SQB 174080
#define SKB 174208
#define ATTN_SMEM 174464

#define SWZ(g, r) ((((g) & 24) | (((g) ^ (r)) & 7)) << 4)

__global__ __launch_bounds__(256) void attn_mma(AttnSide A0, AttnSide A1)
{
    extern __shared__ char smx[];
    const uint32_t sb = smem_to_u32(smx);
    float* den4 = (float*)(smx + SDEN);
    float* qpS  = (float*)(smx + SQP);
    float* kpS  = (float*)(smx + SKP);
    int*   qbS  = (int*)(smx + SQB);
    int*   kbS  = (int*)(smx + SKB);

    const bool first = (blockIdx.x < (unsigned)A0.nblk);
    AttnSide S = first ? A0 : A1;
    const int blk  = first ? blockIdx.x : blockIdx.x - A0.nblk;
    const int sp   = (S.nsplit > 1) ? blk % S.nsplit : 0;
    const int qblk = (S.nsplit > 1) ? blk / S.nsplit : blk;
    const int tid = threadIdx.x, lane = tid & 31, wid = tid >> 5;
    const int wm = wid & 1, wn = wid >> 1;
    const int sub = lane >> 3, r8 = lane & 7;
    const int t4 = lane >> 2, qq = lane & 3;
    const int q0 = qblk * 32;

    // stage Q (both planes, swizzled, cp.async) + qb/qp; zero den partials
#pragma unroll
    for (int it = 0; it < 8; ++it) {
        int idx = tid + it * 256;
        int pl = idx >> 10, r = (idx >> 5) & 31, g = idx & 31;
        uint32_t dst = sb + (pl ? SQL : SQH) + r * 512 + SWZ(g, r);
        const void* src = (pl ? S.Ql : S.Qh) + (size_t)(q0 + r) * DD + g * 8;
        CP_ASYNC16(dst, src, 16);
    }
    CP_COMMIT();
    if (tid < 128) den4[tid] = 0.f;
    if (tid < 32) {
        int r = q0 + tid;
        qbS[tid] = S.qbatch[r];
        qpS[tid * 4 + 0] = S.qpos[r * 3 + 0];
        qpS[tid * 4 + 1] = S.qpos[r * 3 + 1];
        qpS[tid * 4 + 2] = S.qpos[r * 3 + 2];
        qpS[tid * 4 + 3] = 0.f;
    }
    CP_WAIT0();
    __syncthreads();

    const int js = S.kstart[qbS[0]];
    const int bL = qbS[31];
    const int je = S.kstart[bL] + S.kcount[bL];
    const int nch = (je - js + 63) >> 6;
    const int cA = (S.nsplit > 1) ? (sp * nch) / S.nsplit : 0;
    const int cB = (S.nsplit > 1) ? ((sp + 1) * nch) / S.nsplit : nch;

    // K staging (hi+lo, 64 rows) + kb/kp side-table for chunk c
    auto issue_k = [&](int c) {
        const int j0 = js + c * 64;
#pragma unroll
        for (int it = 0; it < 16; ++it) {
            int idx = tid + it * 256;
            int sel = idx >> 11, r = (idx >> 5) & 63, g = idx & 31;
            int gj = j0 + r;
            const __nv_bfloat16* bp = sel ? S.Kl : S.Kh;
            uint32_t dst = sb + SKH + sel * 32768 + r * 512 + SWZ(g, r);
            CP_ASYNC16(dst, (const void*)(bp + (size_t)gj * DD + g * 8), (gj < je) ? 16 : 0);
        }
        if (tid < 64) {
            int gj = j0 + tid;
            if (gj < je) {
                kbS[tid] = S.kbatch[gj];
                kpS[tid * 4 + 0] = S.kpos[gj * 3 + 0];
                kpS[tid * 4 + 1] = S.kpos[gj * 3 + 1];
                kpS[tid * 4 + 2] = S.kpos[gj * 3 + 2];
            } else {
                kbS[tid] = -1;
                kpS[tid * 4 + 0] = 0.f; kpS[tid * 4 + 1] = 0.f; kpS[tid * 4 + 2] = 0.f;
            }
        }
        CP_COMMIT();
    };
    auto issue_v = [&](int c) {
        const int j0 = js + c * 64;
#pragma unroll
        for (int it = 0; it < 16; ++it) {
            int idx = tid + it * 256;
            int sel = idx >> 11, r = (idx >> 5) & 63, g = idx & 31;
            int gj = j0 + r;
            const __nv_bfloat16* bp = sel ? S.Vl : S.Vh;
            uint32_t dst = sb + SVH + sel * 32768 + r * 512 + SWZ(g, r);
            CP_ASYNC16(dst, (const void*)(bp + (size_t)gj * DD + g * 8), (gj < je) ? 16 : 0);
        }
        CP_COMMIT();
    };

    const int er0 = wm * 16 + t4, er1 = er0 + 8;
    const int arow = wm * 16 + (sub & 1) * 8 + r8;
    const int brow = wn * 16 + (sub >> 1) * 8 + r8;
    const float qx0 = qpS[er0 * 4], qy0 = qpS[er0 * 4 + 1], qz0 = qpS[er0 * 4 + 2];
    const float qx1 = qpS[er1 * 4], qy1 = qpS[er1 * 4 + 1], qz1 = qpS[er1 * 4 + 2];
    const int qb0 = qbS[er0], qb1 = qbS[er1];

    float cO[8][4];
#pragma unroll
    for (int i = 0; i < 8; ++i)
#pragma unroll
        for (int j = 0; j < 4; ++j) cO[i][j] = 0.f;

    if (cA < cB) { issue_k(cA); issue_v(cA); }   // groups: K(c), V(c)
    for (int c = cA; c < cB; ++c) {
        CP_WAIT1();          // K(c) complete (V(c) is the newest pending group)
        __syncthreads();     // (a) all threads' K waits done; kb/kp visible

        // ---- S = Q @ K^T : warp tile 16x16 over k=256 ----
        float cS[2][4];
#pragma unroll
        for (int j = 0; j < 4; ++j) { cS[0][j] = 0.f; cS[1][j] = 0.f; }
#pragma unroll
        for (int ks = 0; ks < 16; ++ks) {
            uint32_t ah[4], al[4], bh[4], bl[4];
            int ag = ks * 2 + (sub >> 1);
            uint32_t ao = sb + SQH + arow * 512 + SWZ(ag, arow);
            LDSM_X4(ah, ao);
            LDSM_X4(al, ao + 16384);
            int bg = ks * 2 + (sub & 1);
            uint32_t bo = sb + SKH + brow * 512 + SWZ(bg, brow);
            LDSM_X4(bh, bo);
            LDSM_X4(bl, bo + 32768);
            MMA_BF16(cS[0], ah, bh[0], bh[1]); MMA_BF16(cS[1], ah, bh[2], bh[3]);
            MMA_BF16(cS[0], ah, bl[0], bl[1]); MMA_BF16(cS[1], ah, bl[2], bl[3]);
            MMA_BF16(cS[0], al, bh[0], bh[1]); MMA_BF16(cS[1], al, bh[2], bh[3]);
        }

        // ---- softmax weights, write P hi/lo, accumulate denominators ----
        float rs0 = 0.f, rs1 = 0.f;
#pragma unroll
        for (int nt = 0; nt < 2; ++nt) {
            int kc = wn * 16 + nt * 8 + qq * 2;
            float p[4];
#pragma unroll
            for (int e = 0; e < 4; ++e) {
                int cc = kc + (e & 1);
                float qx = (e < 2) ? qx0 : qx1, qy = (e < 2) ? qy0 : qy1;
                float qz = (e < 2) ? qz0 : qz1;
                int qbv = (e < 2) ? qb0 : qb1;
                float dx = qx - kpS[cc * 4], dy = qy - kpS[cc * 4 + 1];
                float dz = qz - kpS[cc * 4 + 2];
                float d2 = fmaxf(fmaf(dx, dx, fmaf(dy, dy, dz * dz)), 1e-12f);
                p[e] = (qbv == kbS[cc])
                       ? __expf(cS[nt][e] + __expf(-0.1f * sqrtf(d2))) : 0.f;
            }
            rs0 += p[0] + p[1];
            rs1 += p[2] + p[3];
            int g = wn * 2 + nt;
            uint32_t h0, l0, h1, l1;
            split2(p[0], p[1], h0, l0);
            split2(p[2], p[3], h1, l1);
            int o0 = er0 * 128 + (((g ^ (er0 & 7)) & 7) << 4) + qq * 4;
            int o1 = er1 * 128 + (((g ^ (er1 & 7)) & 7) << 4) + qq * 4;
            *(uint32_t*)(smx + SPH + o0) = h0; *(uint32_t*)(smx + SPL + o0) = l0;
            *(uint32_t*)(smx + SPH + o1) = h1; *(uint32_t*)(smx + SPL + o1) = l1;
        }
        rs0 += __shfl_xor_sync(0xffffffffu, rs0, 1);
        rs0 += __shfl_xor_sync(0xffffffffu, rs0, 2);
        rs1 += __shfl_xor_sync(0xffffffffu, rs1, 1);
        rs1 += __shfl_xor_sync(0xffffffffu, rs1, 2);
        if (qq == 0) { den4[wn * 32 + er0] += rs0; den4[wn * 32 + er1] += rs1; }
        __syncthreads();     // (b) K dead, P visible, kp/kb dead

        if (c + 1 < cB) { issue_k(c + 1); CP_WAIT1(); }   // V(c) done; K(c+1) in flight
        else            { CP_WAIT0(); }                   // V(c) done
        __syncthreads();     // (c) all threads' V waits done

        // ---- O += P @ V : warp tile 16x64 over k=64 keys ----
#pragma unroll
        for (int ks = 0; ks < 4; ++ks) {
            uint32_t ph[4], pl[4];
            int pg = ks * 2 + (sub >> 1);
            uint32_t po = sb + SPH + arow * 128 + (((pg ^ (arow & 7)) & 7) << 4);
            LDSM_X4(ph, po);
            LDSM_X4(pl, po + 4096);
            int key = ks * 16 + (sub & 1) * 8 + r8;
#pragma unroll
            for (int nt2 = 0; nt2 < 4; ++nt2) {
                int ng = wn * 8 + nt2 * 2 + (sub >> 1);
                uint32_t vo = sb + SVH + key * 512 + SWZ(ng, key);
                uint32_t vh[4], vl[4];
                LDSM_X4T(vh, vo);
                LDSM_X4T(vl, vo + 32768);
                MMA_BF16(cO[nt2 * 2],     ph, vh[0], vh[1]);
                MMA_BF16(cO[nt2 * 2 + 1], ph, vh[2], vh[3]);
                MMA_BF16(cO[nt2 * 2],     ph, vl[0], vl[1]);
                MMA_BF16(cO[nt2 * 2 + 1], ph, vl[2], vl[3]);
                MMA_BF16(cO[nt2 * 2],     pl, vh[0], vh[1]);
                MMA_BF16(cO[nt2 * 2 + 1], pl, vh[2], vh[3]);
            }
        }
        __syncthreads();     // (d) V dead
        if (c + 1 < cB) issue_v(c + 1);   // lands during S(c+1)
    }
    __syncthreads();

    float d0 = den4[er0] + den4[32 + er0] + den4[64 + er0] + den4[96 + er0];
    float d1 = den4[er1] + den4[32 + er1] + den4[64 + er1] + den4[96 + er1];
    if (S.nsplit == 1) {
        float i0 = 1.0f / d0, i1 = 1.0f / d1;
#pragma unroll
        for (int nt = 0; nt < 8; ++nt) {
            int col = wn * 64 + nt * 8 + qq * 2;
            uint32_t h0, l0, h1, l1;
            split2(cO[nt][0] * i0, cO[nt][1] * i0, h0, l0);
            split2(cO[nt][2] * i1, cO[nt][3] * i1, h1, l1);
            *(uint32_t*)(S.ctxH + (size_t)(q0 + er0) * DD + col) = h0;
            *(uint32_t*)(S.ctxL + (size_t)(q0 + er0) * DD + col) = l0;
            *(uint32_t*)(S.ctxH + (size_t)(q0 + er1) * DD + col) = h1;
            *(uint32_t*)(S.ctxL + (size_t)(q0 + er1) * DD + col) = l1;
        }
    } else {
        size_t base = (size_t)sp * S.prows;
#pragma unroll
        for (int nt = 0; nt < 8; ++nt) {
            int col = wn * 64 + nt * 8 + qq * 2;
            *(float2*)(S.ctxp + (base + q0 + er0) * DD + col) =
                make_float2(cO[nt][0], cO[nt][1]);
            *(float2*)(S.ctxp + (base + q0 + er1) * DD + col) =
                make_float2(cO[nt][2], cO[nt][3]);
        }
        if (tid < 32)
            S.den[base + q0 + tid] =
                den4[tid] + den4[32 + tid] + den4[64 + tid] + den4[96 + tid];
    }
}

// ---------------- merge lig split-K partials -> bf16 hi/lo -------------------
__global__ __launch_bounds__(128) void norm_kernel(
    const float* __restrict__ part, const float* __restrict__ den,
    __nv_bfloat16* __restrict__ ctxH, __nv_bfloat16* __restrict__ ctxL)
{
    const int row = blockIdx.x * 4 + (threadIdx.x >> 5);
    const int lane = threadIdx.x & 31;
    float d = 0.f;
#pragma unroll
    for (int s = 0; s < SPLITS; ++s) d += den[s * NLIG + row];
    const float inv = 1.0f / d;
#pragma unroll
    for (int h = 0; h < 2; ++h) {
        int c = lane * 4 + h * 128;
        float4 a = make_float4(0.f, 0.f, 0.f, 0.f);
#pragma unroll
        for (int s = 0; s < SPLITS; ++s) {
            float4 v = *(const float4*)(part + ((size_t)s * NLIG + row) * DD + c);
            a.x += v.x; a.y += v.y; a.z += v.z; a.w += v.w;
        }
        uint32_t h0, l0, h1, l1;
        split2(a.x * inv, a.y * inv, h0, l0);
        split2(a.z * inv, a.w * inv, h1, l1);
        *(uint2*)(ctxH + (size_t)row * DD + c) = make_uint2(h0, h1);
        *(uint2*)(ctxL + (size_t)row * DD + c) = make_uint2(l0, l1);
    }
}

// ---------------- residual + bias + layernorm -------------------------------
__global__ __launch_bounds__(128) void ln2_kernel(
    const float* __restrict__ lig, const float* __restrict__ pro,
    const float* __restrict__ tL, const float* __restrict__ tP,
    const float* __restrict__ boutL, const float* __restrict__ boutP,
    const float* __restrict__ gL, const float* __restrict__ bL,
    const float* __restrict__ gP, const float* __restrict__ bP,
    float* __restrict__ out)
{
    const int row = blockIdx.x * 4 + (threadIdx.x >> 5);
    const int lane = threadIdx.x & 31;
    const float *x, *y, *bias, *g, *bb;
    if (row < NLIG) {
        x = lig + (size_t)row * DD; y = tL + (size_t)row * DD;
        bias = boutL; g = gL; bb = bL;
    } else {
        int r = row - NLIG;
        x = pro + (size_t)r * DD; y = tP + (size_t)r * DD;
        bias = boutP; g = gP; bb = bP;
    }
    float t[8];
#pragma unroll
    for (int i = 0; i < 8; ++i) {
        int c = lane * 8 + i;
        t[i] = x[c] + y[c] + bias[c];
    }
    float s = 0.f;
#pragma unroll
    for (int i = 0; i < 8; ++i) s += t[i];
#pragma unroll
    for (int off = 16; off; off >>= 1) s += __shfl_xor_sync(0xffffffffu, s, off);
    float mu = s * (1.0f / DD);
    float v = 0.f;
#pragma unroll
    for (int i = 0; i < 8; ++i) { float d = t[i] - mu; v += d * d; }
#pragma unroll
    for (int off = 16; off; off >>= 1) v += __shfl_xor_sync(0xffffffffu, v, off);
    float r = rsqrtf(v * (1.0f / DD) + 1e-5f);
#pragma unroll
    for (int i = 0; i < 8; ++i) {
        int c = lane * 8 + i;
        out[(size_t)row * DD + c] = (t[i] - mu) * r * g[c] + bb[c];
    }
}

// ---------------- launch ----------------------------------------------------
extern "C" void kernel_launch(void* const* d_in, const int* in_sizes, int n_in,
                              void* d_out, int out_size)
{
    const float* lig      = (const float*)d_in[0];
    const float* pro      = (const float*)d_in[1];
    const float* lig_pos  = (const float*)d_in[2];
    const float* pro_pos  = (const float*)d_in[3];
    const int*   lig_batch= (const int*)  d_in[4];
    const int*   pro_batch= (const int*)  d_in[5];
    const float* Wq_lig   = (const float*)d_in[6];
    const float* Wk_pro   = (const float*)d_in[7];
    const float* Wv_pro   = (const float*)d_in[8];
    const float* Wq_pro   = (const float*)d_in[9];
    const float* Wk_lig   = (const float*)d_in[10];
    const float* Wv_lig   = (const float*)d_in[11];
    const float* Wout_lig = (const float*)d_in[12];
    const float* bout_lig = (const float*)d_in[13];
    const float* Wout_pro = (const float*)d_in[14];
    const float* bout_pro = (const float*)d_in[15];
    const float* gl       = (const float*)d_in[16];
    const float* bl       = (const float*)d_in[17];
    const float* gp       = (const float*)d_in[18];
    const float* bp       = (const float*)d_in[19];
    float* out = (float*)d_out;

    float *tmpL, *tmpP, *ctxLp, *denLp;
    int *ls, *lc, *ps, *pc;
    __nv_bfloat16 *ligH, *ligL, *proH, *proL, *WH, *WL;
    __nv_bfloat16 *QH, *QL, *K2H, *K2L, *V2H, *V2L, *KH, *KL, *VH, *VL, *Q2H, *Q2L;
    __nv_bfloat16 *cLH, *cLL, *cPH, *cPL;
    cudaGetSymbolAddress((void**)&tmpL, g_tmpL);
    cudaGetSymbolAddress((void**)&tmpP, g_tmpP);
    cudaGetSymbolAddress((void**)&ctxLp, g_ctxLp);
    cudaGetSymbolAddress((void**)&denLp, g_denLp);
    cudaGetSymbolAddress((void**)&ls, g_ls);
    cudaGetSymbolAddress((void**)&lc, g_lc);
    cudaGetSymbolAddress((void**)&ps, g_ps);
    cudaGetSymbolAddress((void**)&pc, g_pc);
    cudaGetSymbolAddress((void**)&ligH, g_ligH);
    cudaGetSymbolAddress((void**)&ligL, g_ligL);
    cudaGetSymbolAddress((void**)&proH, g_proH);
    cudaGetSymbolAddress((void**)&proL, g_proL);
    cudaGetSymbolAddress((void**)&WH, g_WH);
    cudaGetSymbolAddress((void**)&WL, g_WL);
    cudaGetSymbolAddress((void**)&QH, g_QH);   cudaGetSymbolAddress((void**)&QL, g_QL);
    cudaGetSymbolAddress((void**)&K2H, g_K2H); cudaGetSymbolAddress((void**)&K2L, g_K2L);
    cudaGetSymbolAddress((void**)&V2H, g_V2H); cudaGetSymbolAddress((void**)&V2L, g_V2L);
    cudaGetSymbolAddress((void**)&KH, g_KH);   cudaGetSymbolAddress((void**)&KL, g_KL);
    cudaGetSymbolAddress((void**)&VH, g_VH);   cudaGetSymbolAddress((void**)&VL, g_VL);
    cudaGetSymbolAddress((void**)&Q2H, g_Q2H); cudaGetSymbolAddress((void**)&Q2L, g_Q2L);
    cudaGetSymbolAddress((void**)&cLH, g_cLH); cudaGetSymbolAddress((void**)&cLL, g_cLL);
    cudaGetSymbolAddress((void**)&cPH, g_cPH); cudaGetSymbolAddress((void**)&cPL, g_cPL);

    cudaFuncSetAttribute(gemm_mma, cudaFuncAttributeMaxDynamicSharedMemorySize, GEMM_SMEM);
    cudaFuncSetAttribute(attn_mma, cudaFuncAttributeMaxDynamicSharedMemorySize, ATTN_SMEM);

    ranges_kernel<<<1, 64>>>(lig_batch, pro_batch);

    const float* Wsrc[8] = {Wq_lig, Wk_lig, Wv_lig, Wk_pro, Wv_pro, Wq_pro, Wout_lig, Wout_pro};
    ConvOps c1;
    c1.src[0] = lig; c1.h[0] = ligH; c1.l[0] = ligL; c1.n4[0] = NLIG * DD / 4;
    c1.src[1] = pro; c1.h[1] = proH; c1.l[1] = proL; c1.n4[1] = NPRO * DD / 4;
    for (int i = 0; i < 8; ++i) {
        c1.src[2 + i] = Wsrc[i];
        c1.h[2 + i] = WH + i * DD * DD;
        c1.l[2 + i] = WL + i * DD * DD;
        c1.n4[2 + i] = DD * DD / 4;
    }
    convert_kernel<<<dim3(128, 10), 256>>>(c1);

    // QKV projections -> bf16 hi/lo planes (Q sides pre-scaled by 1/16)
    MmaOps gq;
    for (int i = 0; i < 3; ++i) { gq.Xh[i] = ligH; gq.Xl[i] = ligL; }
    for (int i = 3; i < 6; ++i) { gq.Xh[i] = proH; gq.Xl[i] = proL; }
    for (int i = 0; i < 6; ++i) {
        gq.Wh[i] = WH + i * DD * DD;
        gq.Wl[i] = WL + i * DD * DD;
        gq.Y[i] = nullptr;
        gq.scale[i] = 1.0f;
    }
    gq.Yh[0] = QH;  gq.Yl[0] = QL;  gq.scale[0] = 0.0625f;
    gq.Yh[1] = K2H; gq.Yl[1] = K2L;
    gq.Yh[2] = V2H; gq.Yl[2] = V2L;
    gq.Yh[3] = KH;  gq.Yl[3] = KL;
    gq.Yh[4] = VH;  gq.Yl[4] = VL;
    gq.Yh[5] = Q2H; gq.Yl[5] = Q2L; gq.scale[5] = 0.0625f;
    gq.lig_ops = 3;
    gemm_mma<<<dim3(3 * 16 + 3 * 128, 2), 256, GEMM_SMEM>>>(gq);

    // attention (lig split-K x4 first, then pro); 32 queries per block
    AttnSide aL, aP;
    aL.Qh = QH; aL.Ql = QL; aL.Kh = KH; aL.Kl = KL; aL.Vh = VH; aL.Vl = VL;
    aL.qpos = lig_pos; aL.kpos = pro_pos;
    aL.qbatch = lig_batch; aL.kbatch = pro_batch; aL.kstart = ps; aL.kcount = pc;
    aL.ctxp = ctxLp; aL.den = denLp; aL.ctxH = cLH; aL.ctxL = cLL;
    aL.nblk = (NLIG / 32) * SPLITS; aL.nsplit = SPLITS; aL.prows = NLIG;
    aP.Qh = Q2H; aP.Ql = Q2L; aP.Kh = K2H; aP.Kl = K2L; aP.Vh = V2H; aP.Vl = V2L;
    aP.qpos = pro_pos; aP.kpos = lig_pos;
    aP.qbatch = pro_batch; aP.kbatch = lig_batch; aP.kstart = ls; aP.kcount = lc;
    aP.ctxp = ctxLp; aP.den = denLp; aP.ctxH = cPH; aP.ctxL = cPL;
    aP.nblk = NPRO / 32; aP.nsplit = 1; aP.prows = NPRO;
    attn_mma<<<aL.nblk + aP.nblk, 256, ATTN_SMEM>>>(aL, aP);

    norm_kernel<<<NLIG / 4, 128>>>(ctxLp, denLp, cLH, cLL);

    // output projections (fp32 epilogue)
    MmaOps go;
    for (int i = 0; i < 6; ++i) {
        go.Xh[i] = cLH; go.Xl[i] = cLL;
        go.Wh[i] = WH + 6 * DD * DD; go.Wl[i] = WL + 6 * DD * DD;
        go.Y[i] = tmpL; go.Yh[i] = nullptr; go.Yl[i] = nullptr;
        go.scale[i] = 1.0f;
    }
    go.Xh[1] = cPH; go.Xl[1] = cPL;
    go.Wh[1] = WH + 7 * DD * DD; go.Wl[1] = WL + 7 * DD * DD;
    go.Y[1] = tmpP;
    go.lig_ops = 1;
    gemm_mma<<<dim3(16 + 128, 2), 256, GEMM_SMEM>>>(go);

    ln2_kernel<<<(NLIG + NPRO) / 4, 128>>>(lig, pro, tmpL, tmpP,
                                           bout_lig, bout_pro, gl, bl, gp, bp, out);
}

// round 17
// speedup vs baseline: 1.1083x; 1.0454x over previous
#include <cuda_runtime.h>
#include <cuda_bf16.h>
#include <cstdint>

#define DD 256
#define NLIG 2048
#define NPRO 16384
#define NB 32
#define SPLITS 4

__device__ __forceinline__ uint32_t smem_to_u32(const void* p) {
    uint32_t a;
    asm("{ .reg .u64 t; cvta.to.shared.u64 t, %1; cvt.u32.u64 %0, t; }" : "=r"(a) : "l"(p));
    return a;
}
#define MMA_BF16(c, a, b0v, b1v) \
    asm volatile("mma.sync.aligned.m16n8k16.row.col.f32.bf16.bf16.f32 " \
        "{%0,%1,%2,%3}, {%4,%5,%6,%7}, {%8,%9}, {%0,%1,%2,%3};" \
        : "+f"((c)[0]), "+f"((c)[1]), "+f"((c)[2]), "+f"((c)[3]) \
        : "r"((a)[0]), "r"((a)[1]), "r"((a)[2]), "r"((a)[3]), "r"(b0v), "r"(b1v))
#define LDSM_X4(r, addr) \
    asm volatile("ldmatrix.sync.aligned.m8n8.x4.shared.b16 {%0,%1,%2,%3}, [%4];" \
        : "=r"((r)[0]), "=r"((r)[1]), "=r"((r)[2]), "=r"((r)[3]) : "r"(addr))
#define LDSM_X4T(r, addr) \
    asm volatile("ldmatrix.sync.aligned.m8n8.x4.trans.shared.b16 {%0,%1,%2,%3}, [%4];" \
        : "=r"((r)[0]), "=r"((r)[1]), "=r"((r)[2]), "=r"((r)[3]) : "r"(addr))
#define CP_ASYNC16(dst, src, n) \
    asm volatile("cp.async.cg.shared.global [%0], [%1], 16, %2;" \
        :: "r"(dst), "l"(src), "r"(n))
#define CP_COMMIT() asm volatile("cp.async.commit_group;" ::: "memory")
#define CP_WAIT0()  asm volatile("cp.async.wait_group 0;" ::: "memory")
#define CP_WAIT1()  asm volatile("cp.async.wait_group 1;" ::: "memory")

// ---------------- scratch ---------------------------------------------------
__device__ float g_tmpL[NLIG * DD];
__device__ float g_tmpP[NPRO * DD];
__device__ float g_ctxLp[SPLITS * NLIG * DD];
__device__ float g_denLp[SPLITS * NLIG];
__device__ int g_ls[NB], g_lc[NB], g_ps[NB], g_pc[NB];

__device__ __nv_bfloat16 g_ligH[NLIG * DD], g_ligL[NLIG * DD];
__device__ __nv_bfloat16 g_proH[NPRO * DD], g_proL[NPRO * DD];
__device__ __nv_bfloat16 g_QH [NLIG * DD], g_QL [NLIG * DD];
__device__ __nv_bfloat16 g_K2H[NLIG * DD], g_K2L[NLIG * DD];
__device__ __nv_bfloat16 g_V2H[NLIG * DD], g_V2L[NLIG * DD];
__device__ __nv_bfloat16 g_KH [NPRO * DD], g_KL [NPRO * DD];
__device__ __nv_bfloat16 g_VH [NPRO * DD], g_VL [NPRO * DD];
__device__ __nv_bfloat16 g_Q2H[NPRO * DD], g_Q2L[NPRO * DD];
__device__ __nv_bfloat16 g_cLH[NLIG * DD], g_cLL[NLIG * DD];
__device__ __nv_bfloat16 g_cPH[NPRO * DD], g_cPL[NPRO * DD];
__device__ __nv_bfloat16 g_WH [8 * DD * DD], g_WL[8 * DD * DD];

__device__ __forceinline__ void split2(float a, float b, uint32_t& hi, uint32_t& lo)
{
    __nv_bfloat16 ha = __float2bfloat16(a), hb = __float2bfloat16(b);
    __nv_bfloat162 hp = __halves2bfloat162(ha, hb);
    hi = *reinterpret_cast<uint32_t*>(&hp);
    float la = a - __bfloat162float(ha);
    float lb = b - __bfloat162float(hb);
    __nv_bfloat162 lp = __floats2bfloat162_rn(la, lb);
    lo = *reinterpret_cast<uint32_t*>(&lp);
}

struct ConvOps {
    const float* src[10];
    __nv_bfloat16 *h[10], *l[10];
    int n4[10];
};

__global__ __launch_bounds__(256) void convert_kernel(ConvOps C)
{
    const int op = blockIdx.y;
    const float* __restrict__ s = C.src[op];
    __nv_bfloat16* __restrict__ h = C.h[op];
    __nv_bfloat16* __restrict__ l = C.l[op];
    const int n4 = C.n4[op];
    for (int i = blockIdx.x * 256 + threadIdx.x; i < n4; i += gridDim.x * 256) {
        float4 f = *(const float4*)(s + i * 4);
        uint32_t h0, l0, h1, l1;
        split2(f.x, f.y, h0, l0);
        split2(f.z, f.w, h1, l1);
        *(uint2*)(h + i * 4) = make_uint2(h0, h1);
        *(uint2*)(l + i * 4) = make_uint2(l0, l1);
    }
}

__global__ void ranges_kernel(const int* __restrict__ lb, const int* __restrict__ pb)
{
    int t = threadIdx.x;
    if (t < NB) {
        int b = t, lo = 0, hi = NLIG;
        while (lo < hi) { int m = (lo + hi) >> 1; if (lb[m] < b) lo = m + 1; else hi = m; }
        int s = lo; hi = NLIG;
        while (lo < hi) { int m = (lo + hi) >> 1; if (lb[m] <= b) lo = m + 1; else hi = m; }
        g_ls[b] = s; g_lc[b] = lo - s;
    } else if (t < 2 * NB) {
        int b = t - NB, lo = 0, hi = NPRO;
        while (lo < hi) { int m = (lo + hi) >> 1; if (pb[m] < b) lo = m + 1; else hi = m; }
        int s = lo; hi = NPRO;
        while (lo < hi) { int m = (lo + hi) >> 1; if (pb[m] <= b) lo = m + 1; else hi = m; }
        g_ps[b] = s; g_pc[b] = lo - s;
    }
}

// ============ split-bf16 mma.sync GEMM, 2-stage cp.async pipeline ===========
struct MmaOps {
    const __nv_bfloat16 *Xh[6], *Xl[6], *Wh[6], *Wl[6];
    float* Y[6];
    __nv_bfloat16 *Yh[6], *Yl[6];
    float scale[6];
    int lig_ops;
};

#define GEMM_SMEM 131072

__global__ __launch_bounds__(256) void gemm_mma(MmaOps P)
{
    extern __shared__ char smc[];
    const uint32_t sb = smem_to_u32(smc);

    const int bx = blockIdx.x;
    const int ligregion = P.lig_ops * 16;
    int op, mt;
    if (bx < ligregion) { op = bx >> 4; mt = bx & 15; }
    else { int r = bx - ligregion; op = P.lig_ops + (r >> 7); mt = r & 127; }
    const __nv_bfloat16* __restrict__ Xh = P.Xh[op];
    const __nv_bfloat16* __restrict__ Xl = P.Xl[op];
    const __nv_bfloat16* __restrict__ Wh = P.Wh[op];
    const __nv_bfloat16* __restrict__ Wl = P.Wl[op];
    const int m0 = mt * 128;
    const int n0 = blockIdx.y * 128;

    const int tid = threadIdx.x, lane = tid & 31, wid = tid >> 5;
    const int warpM = wid & 3, warpN = wid >> 2;
    const int sub = lane >> 3, r8 = lane & 7;

    auto issue = [&](int kc, int s) {
        uint32_t st = sb + s * 65536;
#pragma unroll
        for (int it = 0; it < 4; ++it) {
            int idx = tid + it * 256;
            int r = idx >> 3, c8 = idx & 7;
            int byte = (r * 128 + c8 * 16) ^ ((r & 7) << 4);
            size_t goff = (size_t)(m0 + r) * DD + kc * 64 + c8 * 8;
            size_t woff = (size_t)(n0 + r) * DD + kc * 64 + c8 * 8;
            CP_ASYNC16(st + byte,         (const void*)(Xh + goff), 16);
            CP_ASYNC16(st + 16384 + byte, (const void*)(Xl + goff), 16);
            CP_ASYNC16(st + 32768 + byte, (const void*)(Wh + woff), 16);
            CP_ASYNC16(st + 49152 + byte, (const void*)(Wl + woff), 16);
        }
        CP_COMMIT();
    };

    float acc[2][8][4];
#pragma unroll
    for (int i = 0; i < 2; ++i)
#pragma unroll
        for (int j = 0; j < 8; ++j)
#pragma unroll
            for (int k = 0; k < 4; ++k) acc[i][j][k] = 0.f;

    issue(0, 0);
    for (int kc = 0; kc < 4; ++kc) {
        if (kc < 3) issue(kc + 1, (kc + 1) & 1);
        if (kc < 3) { CP_WAIT1(); } else { CP_WAIT0(); }
        __syncthreads();
        const uint32_t st = sb + (kc & 1) * 65536;
#pragma unroll
        for (int k16 = 0; k16 < 4; ++k16) {
            uint32_t a_hi[2][4], a_lo[2][4];
#pragma unroll
            for (int mt2 = 0; mt2 < 2; ++mt2) {
                int row = warpM * 32 + mt2 * 16 + (sub & 1) * 8 + r8;
                int k8  = k16 * 2 + (sub >> 1);
                uint32_t ad = st + ((row * 128 + k8 * 16) ^ ((row & 7) << 4));
                LDSM_X4(a_hi[mt2], ad);
                LDSM_X4(a_lo[mt2], ad + 16384);
            }
#pragma unroll
            for (int np = 0; np < 4; ++np) {
                int nrow = warpN * 64 + np * 16 + (sub >> 1) * 8 + r8;
                int k8   = k16 * 2 + (sub & 1);
                uint32_t bd = st + 32768 + ((nrow * 128 + k8 * 16) ^ ((nrow & 7) << 4));
                uint32_t b_hi[4], b_lo[4];
                LDSM_X4(b_hi, bd);
                LDSM_X4(b_lo, bd + 16384);
#pragma unroll
                for (int mt2 = 0; mt2 < 2; ++mt2) {
                    MMA_BF16(acc[mt2][np * 2],     a_hi[mt2], b_hi[0], b_hi[1]);
                    MMA_BF16(acc[mt2][np * 2 + 1], a_hi[mt2], b_hi[2], b_hi[3]);
                    MMA_BF16(acc[mt2][np * 2],     a_hi[mt2], b_lo[0], b_lo[1]);
                    MMA_BF16(acc[mt2][np * 2 + 1], a_hi[mt2], b_lo[2], b_lo[3]);
                    MMA_BF16(acc[mt2][np * 2],     a_lo[mt2], b_hi[0], b_hi[1]);
                    MMA_BF16(acc[mt2][np * 2 + 1], a_lo[mt2], b_hi[2], b_hi[3]);
                }
            }
        }
        __syncthreads();
    }

    const int t4 = lane >> 2, q = lane & 3;
    __nv_bfloat16* Yh = P.Yh[op];
    if (Yh) {
        __nv_bfloat16* Yl = P.Yl[op];
        const float scl = P.scale[op];
#pragma unroll
        for (int mt2 = 0; mt2 < 2; ++mt2) {
#pragma unroll
            for (int nt = 0; nt < 8; ++nt) {
                int row = m0 + warpM * 32 + mt2 * 16 + t4;
                int col = n0 + warpN * 64 + nt * 8 + q * 2;
                uint32_t h0, l0, h1, l1;
                split2(acc[mt2][nt][0] * scl, acc[mt2][nt][1] * scl, h0, l0);
                split2(acc[mt2][nt][2] * scl, acc[mt2][nt][3] * scl, h1, l1);
                *(uint32_t*)(Yh + (size_t)row * DD + col) = h0;
                *(uint32_t*)(Yl + (size_t)row * DD + col) = l0;
                *(uint32_t*)(Yh + (size_t)(row + 8) * DD + col) = h1;
                *(uint32_t*)(Yl + (size_t)(row + 8) * DD + col) = l1;
            }
        }
    } else {
        float* __restrict__ Y = P.Y[op];
#pragma unroll
        for (int mt2 = 0; mt2 < 2; ++mt2) {
#pragma unroll
            for (int nt = 0; nt < 8; ++nt) {
                float* yr = Y + (size_t)(m0 + warpM * 32 + mt2 * 16 + t4) * DD
                              + n0 + warpN * 64 + nt * 8 + q * 2;
                *(float2*)yr            = make_float2(acc[mt2][nt][0], acc[mt2][nt][1]);
                *(float2*)(yr + 8 * DD) = make_float2(acc[mt2][nt][2], acc[mt2][nt][3]);
            }
        }
    }
}

// == full-MMA flash attention: 32q/CTA, 64-key chunks, phase-ordered prefetch ==
// 8 warps = 2(m) x 4(n). S = QK^T 3-pass split; PV single-pass bf16 (error
// ~1e-4, 10x under the 1e-3 gate). K(c+1) after S(c); V(c+1) after PV(c).

struct AttnSide {
    const __nv_bfloat16 *Qh, *Ql, *Kh, *Kl, *Vh, *Vl;
    const float *qpos, *kpos;
    const int *qbatch, *kbatch, *kstart, *kcount;
    float *ctxp, *den;
    __nv_bfloat16 *ctxH, *ctxL;
    int nblk, nsplit, prows;
};

#define SQH 0
#define SQL 16384
#define SKH 32768
#define SKL 65536
#define SVH 98304
#define SPH 163840
#define SDEN 172032
#define SQP 172544
#define SKP 173056
#define SQB 174080
#define SKB 174208
#define ATTN_SMEM 174464

#define SWZ(g, r) ((((g) & 24) | (((g) ^ (r)) & 7)) << 4)

__global__ __launch_bounds__(256) void attn_mma(AttnSide A0, AttnSide A1)
{
    extern __shared__ char smx[];
    const uint32_t sb = smem_to_u32(smx);
    float* den4 = (float*)(smx + SDEN);
    float* qpS  = (float*)(smx + SQP);
    float* kpS  = (float*)(smx + SKP);
    int*   qbS  = (int*)(smx + SQB);
    int*   kbS  = (int*)(smx + SKB);

    const bool first = (blockIdx.x < (unsigned)A0.nblk);
    AttnSide S = first ? A0 : A1;
    const int blk  = first ? blockIdx.x : blockIdx.x - A0.nblk;
    const int sp   = (S.nsplit > 1) ? blk % S.nsplit : 0;
    const int qblk = (S.nsplit > 1) ? blk / S.nsplit : blk;
    const int tid = threadIdx.x, lane = tid & 31, wid = tid >> 5;
    const int wm = wid & 1, wn = wid >> 1;
    const int sub = lane >> 3, r8 = lane & 7;
    const int t4 = lane >> 2, qq = lane & 3;
    const int q0 = qblk * 32;

    // stage Q (both planes, swizzled, cp.async) + qb/qp; zero den partials
#pragma unroll
    for (int it = 0; it < 8; ++it) {
        int idx = tid + it * 256;
        int pl = idx >> 10, r = (idx >> 5) & 31, g = idx & 31;
        uint32_t dst = sb + (pl ? SQL : SQH) + r * 512 + SWZ(g, r);
        const void* src = (pl ? S.Ql : S.Qh) + (size_t)(q0 + r) * DD + g * 8;
        CP_ASYNC16(dst, src, 16);
    }
    CP_COMMIT();
    if (tid < 128) den4[tid] = 0.f;
    if (tid < 32) {
        int r = q0 + tid;
        qbS[tid] = S.qbatch[r];
        qpS[tid * 4 + 0] = S.qpos[r * 3 + 0];
        qpS[tid * 4 + 1] = S.qpos[r * 3 + 1];
        qpS[tid * 4 + 2] = S.qpos[r * 3 + 2];
        qpS[tid * 4 + 3] = 0.f;
    }
    CP_WAIT0();
    __syncthreads();

    const int js = S.kstart[qbS[0]];
    const int bL = qbS[31];
    const int je = S.kstart[bL] + S.kcount[bL];
    const int nch = (je - js + 63) >> 6;
    const int cA = (S.nsplit > 1) ? (sp * nch) / S.nsplit : 0;
    const int cB = (S.nsplit > 1) ? ((sp + 1) * nch) / S.nsplit : nch;

    // K staging (hi+lo, 64 rows) + kb/kp side-table for chunk c
    auto issue_k = [&](int c) {
        const int j0 = js + c * 64;
#pragma unroll
        for (int it = 0; it < 16; ++it) {
            int idx = tid + it * 256;
            int sel = idx >> 11, r = (idx >> 5) & 63, g = idx & 31;
            int gj = j0 + r;
            const __nv_bfloat16* bp = sel ? S.Kl : S.Kh;
            uint32_t dst = sb + SKH + sel * 32768 + r * 512 + SWZ(g, r);
            CP_ASYNC16(dst, (const void*)(bp + (size_t)gj * DD + g * 8), (gj < je) ? 16 : 0);
        }
        if (tid < 64) {
            int gj = j0 + tid;
            if (gj < je) {
                kbS[tid] = S.kbatch[gj];
                kpS[tid * 4 + 0] = S.kpos[gj * 3 + 0];
                kpS[tid * 4 + 1] = S.kpos[gj * 3 + 1];
                kpS[tid * 4 + 2] = S.kpos[gj * 3 + 2];
            } else {
                kbS[tid] = -1;
                kpS[tid * 4 + 0] = 0.f; kpS[tid * 4 + 1] = 0.f; kpS[tid * 4 + 2] = 0.f;
            }
        }
        CP_COMMIT();
    };
    // V staging: hi plane only (single-pass PV)
    auto issue_v = [&](int c) {
        const int j0 = js + c * 64;
#pragma unroll
        for (int it = 0; it < 8; ++it) {
            int idx = tid + it * 256;
            int r = idx >> 5, g = idx & 31;
            int gj = j0 + r;
            uint32_t dst = sb + SVH + r * 512 + SWZ(g, r);
            CP_ASYNC16(dst, (const void*)(S.Vh + (size_t)gj * DD + g * 8), (gj < je) ? 16 : 0);
        }
        CP_COMMIT();
    };

    const int er0 = wm * 16 + t4, er1 = er0 + 8;
    const int arow = wm * 16 + (sub & 1) * 8 + r8;
    const int brow = wn * 16 + (sub >> 1) * 8 + r8;
    const float qx0 = qpS[er0 * 4], qy0 = qpS[er0 * 4 + 1], qz0 = qpS[er0 * 4 + 2];
    const float qx1 = qpS[er1 * 4], qy1 = qpS[er1 * 4 + 1], qz1 = qpS[er1 * 4 + 2];
    const int qb0 = qbS[er0], qb1 = qbS[er1];

    float cO[8][4];
#pragma unroll
    for (int i = 0; i < 8; ++i)
#pragma unroll
        for (int j = 0; j < 4; ++j) cO[i][j] = 0.f;

    if (cA < cB) { issue_k(cA); issue_v(cA); }   // groups: K(c), V(c)
    for (int c = cA; c < cB; ++c) {
        CP_WAIT1();          // K(c) complete (V(c) is the newest pending group)
        __syncthreads();     // (a) all threads' K waits done; kb/kp visible

        // ---- S = Q @ K^T : warp tile 16x16 over k=256 (3-pass split) ----
        float cS[2][4];
#pragma unroll
        for (int j = 0; j < 4; ++j) { cS[0][j] = 0.f; cS[1][j] = 0.f; }
#pragma unroll
        for (int ks = 0; ks < 16; ++ks) {
            uint32_t ah[4], al[4], bh[4], bl[4];
            int ag = ks * 2 + (sub >> 1);
            uint32_t ao = sb + SQH + arow * 512 + SWZ(ag, arow);
            LDSM_X4(ah, ao);
            LDSM_X4(al, ao + 16384);
            int bg = ks * 2 + (sub & 1);
            uint32_t bo = sb + SKH + brow * 512 + SWZ(bg, brow);
            LDSM_X4(bh, bo);
            LDSM_X4(bl, bo + 32768);
            MMA_BF16(cS[0], ah, bh[0], bh[1]); MMA_BF16(cS[1], ah, bh[2], bh[3]);
            MMA_BF16(cS[0], ah, bl[0], bl[1]); MMA_BF16(cS[1], ah, bl[2], bl[3]);
            MMA_BF16(cS[0], al, bh[0], bh[1]); MMA_BF16(cS[1], al, bh[2], bh[3]);
        }

        // ---- softmax weights, write P (bf16 hi only), accumulate den ----
        float rs0 = 0.f, rs1 = 0.f;
#pragma unroll
        for (int nt = 0; nt < 2; ++nt) {
            int kc = wn * 16 + nt * 8 + qq * 2;
            float p[4];
#pragma unroll
            for (int e = 0; e < 4; ++e) {
                int cc = kc + (e & 1);
                float qx = (e < 2) ? qx0 : qx1, qy = (e < 2) ? qy0 : qy1;
                float qz = (e < 2) ? qz0 : qz1;
                int qbv = (e < 2) ? qb0 : qb1;
                float dx = qx - kpS[cc * 4], dy = qy - kpS[cc * 4 + 1];
                float dz = qz - kpS[cc * 4 + 2];
                float d2 = fmaxf(fmaf(dx, dx, fmaf(dy, dy, dz * dz)), 1e-12f);
                p[e] = (qbv == kbS[cc])
                       ? __expf(cS[nt][e] + __expf(-0.1f * sqrtf(d2))) : 0.f;
            }
            rs0 += p[0] + p[1];
            rs1 += p[2] + p[3];
            int g = wn * 2 + nt;
            __nv_bfloat162 hp0 = __floats2bfloat162_rn(p[0], p[1]);
            __nv_bfloat162 hp1 = __floats2bfloat162_rn(p[2], p[3]);
            int o0 = er0 * 128 + (((g ^ (er0 & 7)) & 7) << 4) + qq * 4;
            int o1 = er1 * 128 + (((g ^ (er1 & 7)) & 7) << 4) + qq * 4;
            *(uint32_t*)(smx + SPH + o0) = *reinterpret_cast<uint32_t*>(&hp0);
            *(uint32_t*)(smx + SPH + o1) = *reinterpret_cast<uint32_t*>(&hp1);
        }
        rs0 += __shfl_xor_sync(0xffffffffu, rs0, 1);
        rs0 += __shfl_xor_sync(0xffffffffu, rs0, 2);
        rs1 += __shfl_xor_sync(0xffffffffu, rs1, 1);
        rs1 += __shfl_xor_sync(0xffffffffu, rs1, 2);
        if (qq == 0) { den4[wn * 32 + er0] += rs0; den4[wn * 32 + er1] += rs1; }
        __syncthreads();     // (b) K dead, P visible, kp/kb dead

        if (c + 1 < cB) { issue_k(c + 1); CP_WAIT1(); }   // V(c) done; K(c+1) in flight
        else            { CP_WAIT0(); }                   // V(c) done
        __syncthreads();     // (c) all threads' V waits done

        // ---- O += P @ V : warp tile 16x64 over k=64 keys (single pass) ----
#pragma unroll
        for (int ks = 0; ks < 4; ++ks) {
            uint32_t ph[4];
            int pg = ks * 2 + (sub >> 1);
            uint32_t po = sb + SPH + arow * 128 + (((pg ^ (arow & 7)) & 7) << 4);
            LDSM_X4(ph, po);
            int key = ks * 16 + (sub & 1) * 8 + r8;
#pragma unroll
            for (int nt2 = 0; nt2 < 4; ++nt2) {
                int ng = wn * 8 + nt2 * 2 + (sub >> 1);
                uint32_t vo = sb + SVH + key * 512 + SWZ(ng, key);
                uint32_t vh[4];
                LDSM_X4T(vh, vo);
                MMA_BF16(cO[nt2 * 2],     ph, vh[0], vh[1]);
                MMA_BF16(cO[nt2 * 2 + 1], ph, vh[2], vh[3]);
            }
        }
        __syncthreads();     // (d) V dead
        if (c + 1 < cB) issue_v(c + 1);   // lands during S(c+1)
    }
    __syncthreads();

    float d0 = den4[er0] + den4[32 + er0] + den4[64 + er0] + den4[96 + er0];
    float d1 = den4[er1] + den4[32 + er1] + den4[64 + er1] + den4[96 + er1];
    if (S.nsplit == 1) {
        float i0 = 1.0f / d0, i1 = 1.0f / d1;
#pragma unroll
        for (int nt = 0; nt < 8; ++nt) {
            int col = wn * 64 + nt * 8 + qq * 2;
            uint32_t h0, l0, h1, l1;
            split2(cO[nt][0] * i0, cO[nt][1] * i0, h0, l0);
            split2(cO[nt][2] * i1, cO[nt][3] * i1, h1, l1);
            *(uint32_t*)(S.ctxH + (size_t)(q0 + er0) * DD + col) = h0;
            *(uint32_t*)(S.ctxL + (size_t)(q0 + er0) * DD + col) = l0;
            *(uint32_t*)(S.ctxH + (size_t)(q0 + er1) * DD + col) = h1;
            *(uint32_t*)(S.ctxL + (size_t)(q0 + er1) * DD + col) = l1;
        }
    } else {
        size_t base = (size_t)sp * S.prows;
#pragma unroll
        for (int nt = 0; nt < 8; ++nt) {
            int col = wn * 64 + nt * 8 + qq * 2;
            *(float2*)(S.ctxp + (base + q0 + er0) * DD + col) =
                make_float2(cO[nt][0], cO[nt][1]);
            *(float2*)(S.ctxp + (base + q0 + er1) * DD + col) =
                make_float2(cO[nt][2], cO[nt][3]);
        }
        if (tid < 32)
            S.den[base + q0 + tid] =
                den4[tid] + den4[32 + tid] + den4[64 + tid] + den4[96 + tid];
    }
}

// ---------------- merge lig split-K partials -> bf16 hi/lo -------------------
__global__ __launch_bounds__(128) void norm_kernel(
    const float* __restrict__ part, const float* __restrict__ den,
    __nv_bfloat16* __restrict__ ctxH, __nv_bfloat16* __restrict__ ctxL)
{
    const int row = blockIdx.x * 4 + (threadIdx.x >> 5);
    const int lane = threadIdx.x & 31;
    float d = 0.f;
#pragma unroll
    for (int s = 0; s < SPLITS; ++s) d += den[s * NLIG + row];
    const float inv = 1.0f / d;
#pragma unroll
    for (int h = 0; h < 2; ++h) {
        int c = lane * 4 + h * 128;
        float4 a = make_float4(0.f, 0.f, 0.f, 0.f);
#pragma unroll
        for (int s = 0; s < SPLITS; ++s) {
            float4 v = *(const float4*)(part + ((size_t)s * NLIG + row) * DD + c);
            a.x += v.x; a.y += v.y; a.z += v.z; a.w += v.w;
        }
        uint32_t h0, l0, h1, l1;
        split2(a.x * inv, a.y * inv, h0, l0);
        split2(a.z * inv, a.w * inv, h1, l1);
        *(uint2*)(ctxH + (size_t)row * DD + c) = make_uint2(h0, h1);
        *(uint2*)(ctxL + (size_t)row * DD + c) = make_uint2(l0, l1);
    }
}

// ---------------- residual + bias + layernorm -------------------------------
__global__ __launch_bounds__(128) void ln2_kernel(
    const float* __restrict__ lig, const float* __restrict__ pro,
    const float* __restrict__ tL, const float* __restrict__ tP,
    const float* __restrict__ boutL, const float* __restrict__ boutP,
    const float* __restrict__ gL, const float* __restrict__ bL,
    const float* __restrict__ gP, const float* __restrict__ bP,
    float* __restrict__ out)
{
    const int row = blockIdx.x * 4 + (threadIdx.x >> 5);
    const int lane = threadIdx.x & 31;
    const float *x, *y, *bias, *g, *bb;
    if (row < NLIG) {
        x = lig + (size_t)row * DD; y = tL + (size_t)row * DD;
        bias = boutL; g = gL; bb = bL;
    } else {
        int r = row - NLIG;
        x = pro + (size_t)r * DD; y = tP + (size_t)r * DD;
        bias = boutP; g = gP; bb = bP;
    }
    float t[8];
#pragma unroll
    for (int i = 0; i < 8; ++i) {
        int c = lane * 8 + i;
        t[i] = x[c] + y[c] + bias[c];
    }
    float s = 0.f;
#pragma unroll
    for (int i = 0; i < 8; ++i) s += t[i];
#pragma unroll
    for (int off = 16; off; off >>= 1) s += __shfl_xor_sync(0xffffffffu, s, off);
    float mu = s * (1.0f / DD);
    float v = 0.f;
#pragma unroll
    for (int i = 0; i < 8; ++i) { float d = t[i] - mu; v += d * d; }
#pragma unroll
    for (int off = 16; off; off >>= 1) v += __shfl_xor_sync(0xffffffffu, v, off);
    float r = rsqrtf(v * (1.0f / DD) + 1e-5f);
#pragma unroll
    for (int i = 0; i < 8; ++i) {
        int c = lane * 8 + i;
        out[(size_t)row * DD + c] = (t[i] - mu) * r * g[c] + bb[c];
    }
}

// ---------------- launch ----------------------------------------------------
extern "C" void kernel_launch(void* const* d_in, const int* in_sizes, int n_in,
                              void* d_out, int out_size)
{
    const float* lig      = (const float*)d_in[0];
    const float* pro      = (const float*)d_in[1];
    const float* lig_pos  = (const float*)d_in[2];
    const float* pro_pos  = (const float*)d_in[3];
    const int*   lig_batch= (const int*)  d_in[4];
    const int*   pro_batch= (const int*)  d_in[5];
    const float* Wq_lig   = (const float*)d_in[6];
    const float* Wk_pro   = (const float*)d_in[7];
    const float* Wv_pro   = (const float*)d_in[8];
    const float* Wq_pro   = (const float*)d_in[9];
    const float* Wk_lig   = (const float*)d_in[10];
    const float* Wv_lig   = (const float*)d_in[11];
    const float* Wout_lig = (const float*)d_in[12];
    const float* bout_lig = (const float*)d_in[13];
    const float* Wout_pro = (const float*)d_in[14];
    const float* bout_pro = (const float*)d_in[15];
    const float* gl       = (const float*)d_in[16];
    const float* bl       = (const float*)d_in[17];
    const float* gp       = (const float*)d_in[18];
    const float* bp       = (const float*)d_in[19];
    float* out = (float*)d_out;

    float *tmpL, *tmpP, *ctxLp, *denLp;
    int *ls, *lc, *ps, *pc;
    __nv_bfloat16 *ligH, *ligL, *proH, *proL, *WH, *WL;
    __nv_bfloat16 *QH, *QL, *K2H, *K2L, *V2H, *V2L, *KH, *KL, *VH, *VL, *Q2H, *Q2L;
    __nv_bfloat16 *cLH, *cLL, *cPH, *cPL;
    cudaGetSymbolAddress((void**)&tmpL, g_tmpL);
    cudaGetSymbolAddress((void**)&tmpP, g_tmpP);
    cudaGetSymbolAddress((void**)&ctxLp, g_ctxLp);
    cudaGetSymbolAddress((void**)&denLp, g_denLp);
    cudaGetSymbolAddress((void**)&ls, g_ls);
    cudaGetSymbolAddress((void**)&lc, g_lc);
    cudaGetSymbolAddress((void**)&ps, g_ps);
    cudaGetSymbolAddress((void**)&pc, g_pc);
    cudaGetSymbolAddress((void**)&ligH, g_ligH);
    cudaGetSymbolAddress((void**)&ligL, g_ligL);
    cudaGetSymbolAddress((void**)&proH, g_proH);
    cudaGetSymbolAddress((void**)&proL, g_proL);
    cudaGetSymbolAddress((void**)&WH, g_WH);
    cudaGetSymbolAddress((void**)&WL, g_WL);
    cudaGetSymbolAddress((void**)&QH, g_QH);   cudaGetSymbolAddress((void**)&QL, g_QL);
    cudaGetSymbolAddress((void**)&K2H, g_K2H); cudaGetSymbolAddress((void**)&K2L, g_K2L);
    cudaGetSymbolAddress((void**)&V2H, g_V2H); cudaGetSymbolAddress((void**)&V2L, g_V2L);
    cudaGetSymbolAddress((void**)&KH, g_KH);   cudaGetSymbolAddress((void**)&KL, g_KL);
    cudaGetSymbolAddress((void**)&VH, g_VH);   cudaGetSymbolAddress((void**)&VL, g_VL);
    cudaGetSymbolAddress((void**)&Q2H, g_Q2H); cudaGetSymbolAddress((void**)&Q2L, g_Q2L);
    cudaGetSymbolAddress((void**)&cLH, g_cLH); cudaGetSymbolAddress((void**)&cLL, g_cLL);
    cudaGetSymbolAddress((void**)&cPH, g_cPH); cudaGetSymbolAddress((void**)&cPL, g_cPL);

    cudaFuncSetAttribute(gemm_mma, cudaFuncAttributeMaxDynamicSharedMemorySize, GEMM_SMEM);
    cudaFuncSetAttribute(attn_mma, cudaFuncAttributeMaxDynamicSharedMemorySize, ATTN_SMEM);

    ranges_kernel<<<1, 64>>>(lig_batch, pro_batch);

    const float* Wsrc[8] = {Wq_lig, Wk_lig, Wv_lig, Wk_pro, Wv_pro, Wq_pro, Wout_lig, Wout_pro};
    ConvOps c1;
    c1.src[0] = lig; c1.h[0] = ligH; c1.l[0] = ligL; c1.n4[0] = NLIG * DD / 4;
    c1.src[1] = pro; c1.h[1] = proH; c1.l[1] = proL; c1.n4[1] = NPRO * DD / 4;
    for (int i = 0; i < 8; ++i) {
        c1.src[2 + i] = Wsrc[i];
        c1.h[2 + i] = WH + i * DD * DD;
        c1.l[2 + i] = WL + i * DD * DD;
        c1.n4[2 + i] = DD * DD / 4;
    }
    convert_kernel<<<dim3(128, 10), 256>>>(c1);

    // QKV projections -> bf16 hi/lo planes (Q sides pre-scaled by 1/16)
    MmaOps gq;
    for (int i = 0; i < 3; ++i) { gq.Xh[i] = ligH; gq.Xl[i] = ligL; }
    for (int i = 3; i < 6; ++i) { gq.Xh[i] = proH; gq.Xl[i] = proL; }
    for (int i = 0; i < 6; ++i) {
        gq.Wh[i] = WH + i * DD * DD;
        gq.Wl[i] = WL + i * DD * DD;
        gq.Y[i] = nullptr;
        gq.scale[i] = 1.0f;
    }
    gq.Yh[0] = QH;  gq.Yl[0] = QL;  gq.scale[0] = 0.0625f;
    gq.Yh[1] = K2H; gq.Yl[1] = K2L;
    gq.Yh[2] = V2H; gq.Yl[2] = V2L;
    gq.Yh[3] = KH;  gq.Yl[3] = KL;
    gq.Yh[4] = VH;  gq.Yl[4] = VL;
    gq.Yh[5] = Q2H; gq.Yl[5] = Q2L; gq.scale[5] = 0.0625f;
    gq.lig_ops = 3;
    gemm_mma<<<dim3(3 * 16 + 3 * 128, 2), 256, GEMM_SMEM>>>(gq);

    // attention (lig split-K x4 first, then pro); 32 queries per block
    AttnSide aL, aP;
    aL.Qh = QH; aL.Ql = QL; aL.Kh = KH; aL.Kl = KL; aL.Vh = VH; aL.Vl = VL;
    aL.qpos = lig_pos; aL.kpos = pro_pos;
    aL.qbatch = lig_batch; aL.kbatch = pro_batch; aL.kstart = ps; aL.kcount = pc;
    aL.ctxp = ctxLp; aL.den = denLp; aL.ctxH = cLH; aL.ctxL = cLL;
    aL.nblk = (NLIG / 32) * SPLITS; aL.nsplit = SPLITS; aL.prows = NLIG;
    aP.Qh = Q2H; aP.Ql = Q2L; aP.Kh = K2H; aP.Kl = K2L; aP.Vh = V2H; aP.Vl = V2L;
    aP.qpos = pro_pos; aP.kpos = lig_pos;
    aP.qbatch = pro_batch; aP.kbatch = lig_batch; aP.kstart = ls; aP.kcount = lc;
    aP.ctxp = ctxLp; aP.den = denLp; aP.ctxH = cPH; aP.ctxL = cPL;
    aP.nblk = NPRO / 32; aP.nsplit = 1; aP.prows = NPRO;
    attn_mma<<<aL.nblk + aP.nblk, 256, ATTN_SMEM>>>(aL, aP);

    norm_kernel<<<NLIG / 4, 128>>>(ctxLp, denLp, cLH, cLL);

    // output projections (fp32 epilogue)
    MmaOps go;
    for (int i = 0; i < 6; ++i) {
        go.Xh[i] = cLH; go.Xl[i] = cLL;
        go.Wh[i] = WH + 6 * DD * DD; go.Wl[i] = WL + 6 * DD * DD;
        go.Y[i] = tmpL; go.Yh[i] = nullptr; go.Yl[i] = nullptr;
        go.scale[i] = 1.0f;
    }
    go.Xh[1] = cPH; go.Xl[1] = cPL;
    go.Wh[1] = WH + 7 * DD * DD; go.Wl[1] = WL + 7 * DD * DD;
    go.Y[1] = tmpP;
    go.lig_ops = 1;
    gemm_mma<<<dim3(16 + 128, 2), 256, GEMM_SMEM>>>(go);

    ln2_kernel<<<(NLIG + NPRO) / 4, 128>>>(lig, pro, tmpL, tmpP,
                                           bout_lig, bout_pro, gl, bl, gp, bp, out);
}